// round 2
// baseline (speedup 1.0000x reference)
#include <cuda_runtime.h>
#include <cuda_bf16.h>
#include <math.h>

// Problem constants
#define Bq  16
#define Tq  1024
#define Dq  256
#define Cq  1024
#define Kq  9

// GEMM tiling
#define BM 128
#define BN 128
#define BKT 16
#define TM 8
#define TN 8
// 256 threads = 16x16

// Scratch (device globals: allocation-free)
__device__ float g_h[(size_t)Bq * Cq * Tq];      // mish(w1@x^T+b1)   [b][c][t]
__device__ float g_conv[(size_t)Bq * Cq * Tq];   // depthwise conv    [b][c][t]
__device__ float g_tmp[(size_t)Bq * Cq * Tq];    // mish(pointwise)   [b][o][t]
__device__ float g_inv_pnorm[Bq * Cq];           // 1/max(||p_w[:,o]||,eps)
__device__ float g_inv_dnorm[Bq * Kq];           // 1/max(||d_w[:,k]||,eps)

__device__ __forceinline__ float mishf(float x) {
    // x * tanh(softplus(x)); softplus stable for large x
    float sp = (x > 20.f) ? x : log1pf(__expf(x));
    return x * tanhf(sp);
}

// ---------------------------------------------------------------------------
// Weight-norm denominators
// ---------------------------------------------------------------------------
__global__ void dnorm_kernel(const float* __restrict__ d_w) {
    // grid = B*K blocks, 256 threads; reduce over c
    int bk = blockIdx.x;
    int b = bk / Kq, k = bk % Kq;
    float s = 0.f;
    for (int c = threadIdx.x; c < Cq; c += 256) {
        float v = d_w[((size_t)b * Cq + c) * Kq + k];
        s = fmaf(v, v, s);
    }
    __shared__ float red[256];
    red[threadIdx.x] = s;
    __syncthreads();
    for (int off = 128; off > 0; off >>= 1) {
        if (threadIdx.x < off) red[threadIdx.x] += red[threadIdx.x + off];
        __syncthreads();
    }
    if (threadIdx.x == 0)
        g_inv_dnorm[bk] = 1.f / fmaxf(sqrtf(red[0]), 1e-12f);
}

__global__ void pnorm_kernel(const float* __restrict__ p_w) {
    // grid = (B, 4), 256 threads; each thread owns one o, loops over c
    int b = blockIdx.x;
    int o = blockIdx.y * 256 + threadIdx.x;
    const float* base = p_w + (size_t)b * Cq * Cq + o;
    float s = 0.f;
    #pragma unroll 4
    for (int c = 0; c < Cq; ++c) {
        float v = base[(size_t)c * Cq];
        s = fmaf(v, v, s);
    }
    g_inv_pnorm[b * Cq + o] = 1.f / fmaxf(sqrtf(s), 1e-12f);
}

// ---------------------------------------------------------------------------
// GEMM1: h[b,c,t] = mish( sum_d w1[c,d] * x[b,t,d] + b1[c] )
// A = w1 [C,D] row-major (k contiguous), B = x[b] [T,D] (k contiguous)
// ---------------------------------------------------------------------------
__global__ __launch_bounds__(256) void gemm1_kernel(
    const float* __restrict__ x, const float* __restrict__ w1,
    const float* __restrict__ b1)
{
    int b  = blockIdx.z;
    int m0 = blockIdx.y * BM;   // c
    int n0 = blockIdx.x * BN;   // t
    __shared__ float As[BKT][BM];
    __shared__ float Bs[BKT][BN];
    const float* Ag = w1;
    const float* Bg = x + (size_t)b * Tq * Dq;

    int tid = threadIdx.x;
    int ty = tid >> 4, tx = tid & 15;
    int lr  = tid >> 2;        // 0..63
    int lk4 = (tid & 3) * 4;   // {0,4,8,12}

    float acc[TM][TN] = {};

    for (int k0 = 0; k0 < Dq; k0 += BKT) {
        #pragma unroll
        for (int p = 0; p < 2; ++p) {
            int m = lr + p * 64;
            float4 v = *(const float4*)(Ag + (size_t)(m0 + m) * Dq + k0 + lk4);
            As[lk4 + 0][m] = v.x; As[lk4 + 1][m] = v.y;
            As[lk4 + 2][m] = v.z; As[lk4 + 3][m] = v.w;
        }
        #pragma unroll
        for (int p = 0; p < 2; ++p) {
            int n = lr + p * 64;
            float4 v = *(const float4*)(Bg + (size_t)(n0 + n) * Dq + k0 + lk4);
            Bs[lk4 + 0][n] = v.x; Bs[lk4 + 1][n] = v.y;
            Bs[lk4 + 2][n] = v.z; Bs[lk4 + 3][n] = v.w;
        }
        __syncthreads();
        #pragma unroll
        for (int kk = 0; kk < BKT; ++kk) {
            float a[TM], bb[TN];
            #pragma unroll
            for (int i = 0; i < TM; ++i) a[i]  = As[kk][ty * TM + i];
            #pragma unroll
            for (int j = 0; j < TN; ++j) bb[j] = Bs[kk][tx * TN + j];
            #pragma unroll
            for (int i = 0; i < TM; ++i)
                #pragma unroll
                for (int j = 0; j < TN; ++j)
                    acc[i][j] = fmaf(a[i], bb[j], acc[i][j]);
        }
        __syncthreads();
    }
    #pragma unroll
    for (int i = 0; i < TM; ++i) {
        int m = m0 + ty * TM + i;
        float bias = b1[m];
        float* row = g_h + (size_t)b * Cq * Tq + (size_t)m * Tq + n0 + tx * TN;
        #pragma unroll
        for (int j = 0; j < TN; ++j)
            row[j] = mishf(acc[i][j] + bias);
    }
}

// ---------------------------------------------------------------------------
// Depthwise conv: g_conv[b,c,t] = d_b[b,c] + sum_k h[b,c,t+k-4] * dwn[b,c,k]
// dwn[b,c,k] = d_w[b,c,0,k] * inv_dnorm[b,k] * d_g[b,c]
// ---------------------------------------------------------------------------
__global__ __launch_bounds__(256) void conv_kernel(
    const float* __restrict__ d_w, const float* __restrict__ d_g,
    const float* __restrict__ d_b)
{
    int bc = blockIdx.x;
    int b = bc >> 10;
    int c = bc & 1023;
    __shared__ float s[Tq + 8];
    int tid = threadIdx.x;
    const float* hrow = g_h + (size_t)bc * Tq;
    for (int t = tid; t < Tq; t += 256) s[t + 4] = hrow[t];
    if (tid < 8) s[(tid < 4) ? tid : (Tq + tid)] = 0.f;
    __syncthreads();

    float w[Kq];
    float g = d_g[b * Cq + c];
    #pragma unroll
    for (int k = 0; k < Kq; ++k)
        w[k] = d_w[(size_t)bc * Kq + k] * g_inv_dnorm[b * Kq + k] * g;
    float bias = d_b[b * Cq + c];

    float* orow = g_conv + (size_t)bc * Tq;
    for (int t = tid; t < Tq; t += 256) {
        float acc = bias;
        #pragma unroll
        for (int k = 0; k < Kq; ++k)
            acc = fmaf(s[t + k], w[k], acc);
        orow[t] = acc;
    }
}

// ---------------------------------------------------------------------------
// GEMM2 (dominant): tmp[b,o,t] = mish( inv_pnorm[b,o] *
//          sum_c p_w[b,c,o]*p_g[b,c]*conv[b,c,t]  + p_b[b,o] )
// A column-major in m (p_w: [c][o], o contiguous), B row-major in n.
// ---------------------------------------------------------------------------
__global__ __launch_bounds__(256) void gemm2_kernel(
    const float* __restrict__ p_w, const float* __restrict__ p_g,
    const float* __restrict__ p_b)
{
    int b  = blockIdx.z;
    int m0 = blockIdx.y * BM;   // o
    int n0 = blockIdx.x * BN;   // t
    __shared__ float As[BKT][BM];
    __shared__ float Bs[BKT][BN];
    const float* Ag = p_w + (size_t)b * Cq * Cq;   // [c][o]
    const float* Bg = g_conv + (size_t)b * Cq * Tq; // [c][t]
    const float* pg = p_g + b * Cq;

    int tid = threadIdx.x;
    int ty = tid >> 4, tx = tid & 15;
    int lk  = tid >> 5;        // 0..7
    int lm4 = (tid & 31) * 4;  // 0..124

    float acc[TM][TN] = {};

    for (int k0 = 0; k0 < Cq; k0 += BKT) {
        #pragma unroll
        for (int p = 0; p < 2; ++p) {
            int k = lk + p * 8;
            float gsc = pg[k0 + k];
            float4 v = *(const float4*)(Ag + (size_t)(k0 + k) * Cq + m0 + lm4);
            v.x *= gsc; v.y *= gsc; v.z *= gsc; v.w *= gsc;
            *(float4*)&As[k][lm4] = v;
            float4 u = *(const float4*)(Bg + (size_t)(k0 + k) * Tq + n0 + lm4);
            *(float4*)&Bs[k][lm4] = u;
        }
        __syncthreads();
        #pragma unroll
        for (int kk = 0; kk < BKT; ++kk) {
            float a[TM], bb[TN];
            #pragma unroll
            for (int i = 0; i < TM; ++i) a[i]  = As[kk][ty * TM + i];
            #pragma unroll
            for (int j = 0; j < TN; ++j) bb[j] = Bs[kk][tx * TN + j];
            #pragma unroll
            for (int i = 0; i < TM; ++i)
                #pragma unroll
                for (int j = 0; j < TN; ++j)
                    acc[i][j] = fmaf(a[i], bb[j], acc[i][j]);
        }
        __syncthreads();
    }
    #pragma unroll
    for (int i = 0; i < TM; ++i) {
        int m = m0 + ty * TM + i;
        float s  = g_inv_pnorm[b * Cq + m];
        float pb = p_b[b * Cq + m];
        float* row = g_tmp + (size_t)b * Cq * Tq + (size_t)m * Tq + n0 + tx * TN;
        #pragma unroll
        for (int j = 0; j < TN; ++j)
            row[j] = mishf(acc[i][j] * s + pb);
    }
}

// ---------------------------------------------------------------------------
// GEMM3: out[b,t,d] = sum_c w2[d,c]*tmp[b,c,t] + b2[d] + x[b,t,d]
// A = w2 [D,C] row-major (k contiguous), B = tmp[b] [C,T] (n contiguous)
// Output column-major in m (d contiguous).
// ---------------------------------------------------------------------------
__global__ __launch_bounds__(256) void gemm3_kernel(
    const float* __restrict__ x, const float* __restrict__ w2,
    const float* __restrict__ b2, float* __restrict__ out)
{
    int b  = blockIdx.z;
    int m0 = blockIdx.y * BM;   // d
    int n0 = blockIdx.x * BN;   // t
    __shared__ float As[BKT][BM];
    __shared__ float Bs[BKT][BN];
    const float* Ag = w2;                          // [D][C]
    const float* Bg = g_tmp + (size_t)b * Cq * Tq; // [c][t]

    int tid = threadIdx.x;
    int ty = tid >> 4, tx = tid & 15;
    int lr  = tid >> 2;        // 0..63  (A transpose-load)
    int lk4 = (tid & 3) * 4;
    int lk  = tid >> 5;        // 0..7   (B direct load)
    int lm4 = (tid & 31) * 4;

    float acc[TM][TN] = {};

    for (int k0 = 0; k0 < Cq; k0 += BKT) {
        #pragma unroll
        for (int p = 0; p < 2; ++p) {
            int m = lr + p * 64;
            float4 v = *(const float4*)(Ag + (size_t)(m0 + m) * Cq + k0 + lk4);
            As[lk4 + 0][m] = v.x; As[lk4 + 1][m] = v.y;
            As[lk4 + 2][m] = v.z; As[lk4 + 3][m] = v.w;
        }
        #pragma unroll
        for (int p = 0; p < 2; ++p) {
            int k = lk + p * 8;
            float4 u = *(const float4*)(Bg + (size_t)(k0 + k) * Tq + n0 + lm4);
            *(float4*)&Bs[k][lm4] = u;
        }
        __syncthreads();
        #pragma unroll
        for (int kk = 0; kk < BKT; ++kk) {
            float a[TM], bb[TN];
            #pragma unroll
            for (int i = 0; i < TM; ++i) a[i]  = As[kk][ty * TM + i];
            #pragma unroll
            for (int j = 0; j < TN; ++j) bb[j] = Bs[kk][tx * TN + j];
            #pragma unroll
            for (int i = 0; i < TM; ++i)
                #pragma unroll
                for (int j = 0; j < TN; ++j)
                    acc[i][j] = fmaf(a[i], bb[j], acc[i][j]);
        }
        __syncthreads();
    }
    // out[b][n][m] = acc + b2[m] + x[b][n][m]   (m contiguous)
    float bias[TM];
    #pragma unroll
    for (int i = 0; i < TM; ++i) bias[i] = b2[m0 + ty * TM + i];
    #pragma unroll
    for (int j = 0; j < TN; ++j) {
        int n = n0 + tx * TN + j;
        size_t base = (size_t)b * Tq * Dq + (size_t)n * Dq + m0 + ty * TM;
        #pragma unroll
        for (int i = 0; i < TM; ++i)
            out[base + i] = acc[i][j] + bias[i] + x[base + i];
    }
}

// ---------------------------------------------------------------------------
extern "C" void kernel_launch(void* const* d_in, const int* in_sizes, int n_in,
                              void* d_out, int out_size) {
    const float* x   = (const float*)d_in[0];
    const float* d_w = (const float*)d_in[1];
    const float* d_g = (const float*)d_in[2];
    const float* d_b = (const float*)d_in[3];
    const float* p_w = (const float*)d_in[4];
    const float* p_g = (const float*)d_in[5];
    const float* p_b = (const float*)d_in[6];
    const float* w1  = (const float*)d_in[7];
    const float* b1  = (const float*)d_in[8];
    const float* w2  = (const float*)d_in[9];
    const float* b2  = (const float*)d_in[10];
    float* out = (float*)d_out;

    dnorm_kernel<<<Bq * Kq, 256>>>(d_w);
    pnorm_kernel<<<dim3(Bq, Cq / 256), 256>>>(p_w);
    gemm1_kernel<<<dim3(Tq / BN, Cq / BM, Bq), 256>>>(x, w1, b1);
    conv_kernel<<<Bq * Cq, 256>>>(d_w, d_g, d_b);
    gemm2_kernel<<<dim3(Tq / BN, Cq / BM, Bq), 256>>>(p_w, p_g, p_b);
    gemm3_kernel<<<dim3(Tq / BN, Dq / BM, Bq), 256>>>(x, w2, b2, out);
}

// round 4
// speedup vs baseline: 1.8085x; 1.8085x over previous
#include <cuda_runtime.h>
#include <cuda_bf16.h>
#include <cstdint>
#include <math.h>

#define Bq  16
#define Tq  1024
#define Dq  256
#define Cq  1024
#define Kq  9

// ===========================================================================
// Helpers (baseline PTX only — no 'a'-suffix features)
// ===========================================================================
__device__ __forceinline__ uint32_t smem_to_u32(const void* p) {
    uint32_t a;
    asm("{ .reg .u64 t; cvta.to.shared.u64 t, %1; cvt.u32.u64 %0, t; }" : "=r"(a) : "l"(p));
    return a;
}
__device__ __forceinline__ void cp16(uint32_t sa, const void* g) {
    asm volatile("cp.async.cg.shared.global [%0], [%1], 16;\n" :: "r"(sa), "l"(g));
}
#define CP_COMMIT() asm volatile("cp.async.commit_group;\n" ::: "memory")
#define CP_WAIT1()  asm volatile("cp.async.wait_group 1;\n" ::: "memory")

#define LDSM_X4(r, a) \
    asm volatile("ldmatrix.sync.aligned.m8n8.x4.shared.b16 {%0,%1,%2,%3}, [%4];" \
        : "=r"((r)[0]), "=r"((r)[1]), "=r"((r)[2]), "=r"((r)[3]) : "r"(a))
#define LDSM_X2(r, a) \
    asm volatile("ldmatrix.sync.aligned.m8n8.x2.shared.b16 {%0,%1}, [%2];" \
        : "=r"((r)[0]), "=r"((r)[1]) : "r"(a))

#define MMA_BF16(d, a, bb) \
    asm volatile("mma.sync.aligned.m16n8k16.row.col.f32.bf16.bf16.f32 " \
        "{%0,%1,%2,%3}, {%4,%5,%6,%7}, {%8,%9}, {%0,%1,%2,%3};" \
        : "+f"((d)[0]), "+f"((d)[1]), "+f"((d)[2]), "+f"((d)[3]) \
        : "r"((a)[0]), "r"((a)[1]), "r"((a)[2]), "r"((a)[3]), \
          "r"((bb)[0]), "r"((bb)[1]))

__device__ __forceinline__ float mishf(float x) {
    float sp = (x > 20.f) ? x : log1pf(__expf(x));
    return x * tanhf(sp);
}
__device__ __forceinline__ void bsplit(float v, __nv_bfloat16& h, __nv_bfloat16& l) {
    h = __float2bfloat16(v);
    l = __float2bfloat16(v - __bfloat162float(h));
}

// ===========================================================================
// Device scratch (bf16 split operands; fp32 intermediates)
// ===========================================================================
__device__ __align__(16) __nv_bfloat16 g_xhi[(size_t)Bq * Tq * Dq];
__device__ __align__(16) __nv_bfloat16 g_xlo[(size_t)Bq * Tq * Dq];
__device__ __align__(16) __nv_bfloat16 g_w1hi[(size_t)Cq * Dq];
__device__ __align__(16) __nv_bfloat16 g_w1lo[(size_t)Cq * Dq];
__device__ __align__(16) __nv_bfloat16 g_w2hi[(size_t)Dq * Cq];
__device__ __align__(16) __nv_bfloat16 g_w2lo[(size_t)Dq * Cq];
__device__ __align__(16) float g_hT[(size_t)Bq * Tq * Cq];              // [b][t][c]
__device__ __align__(16) __nv_bfloat16 g_convhi[(size_t)Bq * Tq * Cq];  // [b][t][c]
__device__ __align__(16) __nv_bfloat16 g_convlo[(size_t)Bq * Tq * Cq];
__device__ __align__(16) __nv_bfloat16 g_pwhi[(size_t)Bq * Cq * Cq];    // [b][o][c]
__device__ __align__(16) __nv_bfloat16 g_pwlo[(size_t)Bq * Cq * Cq];
__device__ __align__(16) __nv_bfloat16 g_tmphi[(size_t)Bq * Tq * Cq];   // [b][t][o]
__device__ __align__(16) __nv_bfloat16 g_tmplo[(size_t)Bq * Tq * Cq];
__device__ float g_inv_pnorm[Bq * Cq];
__device__ float g_inv_dnorm[Bq * Kq];

// ===========================================================================
// Prep kernels
// ===========================================================================
__global__ void split_kernel(const float* __restrict__ src,
                             __nv_bfloat16* __restrict__ hi,
                             __nv_bfloat16* __restrict__ lo, int n4) {
    int i = blockIdx.x * 256 + threadIdx.x;
    if (i >= n4) return;
    float4 v = ((const float4*)src)[i];
    __nv_bfloat16 h0, h1, h2, h3, l0, l1, l2, l3;
    bsplit(v.x, h0, l0); bsplit(v.y, h1, l1);
    bsplit(v.z, h2, l2); bsplit(v.w, h3, l3);
    ((__nv_bfloat162*)hi)[2 * i]     = __nv_bfloat162{h0, h1};
    ((__nv_bfloat162*)hi)[2 * i + 1] = __nv_bfloat162{h2, h3};
    ((__nv_bfloat162*)lo)[2 * i]     = __nv_bfloat162{l0, l1};
    ((__nv_bfloat162*)lo)[2 * i + 1] = __nv_bfloat162{l2, l3};
}

__global__ void dnorm_kernel(const float* __restrict__ d_w) {
    int bk = blockIdx.x;
    int b = bk / Kq, k = bk % Kq;
    float s = 0.f;
    for (int c = threadIdx.x; c < Cq; c += 256) {
        float v = d_w[((size_t)b * Cq + c) * Kq + k];
        s = fmaf(v, v, s);
    }
    __shared__ float red[256];
    red[threadIdx.x] = s;
    __syncthreads();
    for (int off = 128; off > 0; off >>= 1) {
        if (threadIdx.x < off) red[threadIdx.x] += red[threadIdx.x + off];
        __syncthreads();
    }
    if (threadIdx.x == 0)
        g_inv_dnorm[bk] = 1.f / fmaxf(sqrtf(red[0]), 1e-12f);
}

__global__ void pnorm_kernel(const float* __restrict__ p_w) {
    int b = blockIdx.x;
    int o = blockIdx.y * 256 + threadIdx.x;
    const float* base = p_w + (size_t)b * Cq * Cq + o;
    float s = 0.f;
    #pragma unroll 4
    for (int c = 0; c < Cq; ++c) {
        float v = base[(size_t)c * Cq];
        s = fmaf(v, v, s);
    }
    g_inv_pnorm[b * Cq + o] = 1.f / fmaxf(sqrtf(s), 1e-12f);
}

// Transpose p_w[b][c][o]*p_g[b][c] -> [b][o][c], bf16 split.
__global__ __launch_bounds__(256) void pw_prep_kernel(
    const float* __restrict__ p_w, const float* __restrict__ p_g) {
    int b = blockIdx.z;
    int c0 = blockIdx.x * 32;
    int o0 = blockIdx.y * 32;
    __shared__ float s[32][33];
    __shared__ float pgs[32];
    int tid = threadIdx.x;
    int x = tid & 31, y = tid >> 5;
    if (tid < 32) pgs[tid] = p_g[b * Cq + c0 + tid];
    const float* in = p_w + (size_t)b * Cq * Cq;
    #pragma unroll
    for (int yy = 0; yy < 4; ++yy) {
        int c = c0 + y * 4 + yy;
        s[y * 4 + yy][x] = in[(size_t)c * Cq + o0 + x];
    }
    __syncthreads();
    __nv_bfloat16* ohi = g_pwhi + (size_t)b * Cq * Cq;
    __nv_bfloat16* olo = g_pwlo + (size_t)b * Cq * Cq;
    #pragma unroll
    for (int yy = 0; yy < 4; ++yy) {
        int o = o0 + y * 4 + yy;
        float w = s[x][y * 4 + yy] * pgs[x];
        __nv_bfloat16 h, l;
        bsplit(w, h, l);
        ohi[(size_t)o * Cq + c0 + x] = h;
        olo[(size_t)o * Cq + c0 + x] = l;
    }
}

// ===========================================================================
// Depthwise conv on [t][c] layout -> bf16 split
// ===========================================================================
__global__ __launch_bounds__(256) void conv_t_kernel(
    const float* __restrict__ d_w, const float* __restrict__ d_g,
    const float* __restrict__ d_b) {
    int b  = blockIdx.z;
    int t0 = blockIdx.y * 8;
    int ch = blockIdx.x * 512;
    __shared__ float s[16][512];
    const float* h = g_hT + (size_t)b * Tq * Cq;
    int tid = threadIdx.x;
    #pragma unroll
    for (int i = 0; i < 8; ++i) {
        int idx = tid + i * 256;
        int r  = idx >> 7;
        int cc = (idx & 127) * 4;
        int t = t0 - 4 + r;
        float4 v = (t >= 0 && t < Tq)
            ? *(const float4*)(h + (size_t)t * Cq + ch + cc)
            : make_float4(0.f, 0.f, 0.f, 0.f);
        *(float4*)&s[r][cc] = v;
    }
    __syncthreads();
    int cg = (tid & 127) * 4;
    int tsub = tid >> 7;
    int c = ch + cg;
    float w[Kq][4], bias[4];
    #pragma unroll
    for (int q = 0; q < 4; ++q) {
        float g = d_g[b * Cq + c + q];
        bias[q] = d_b[b * Cq + c + q];
        #pragma unroll
        for (int k = 0; k < Kq; ++k)
            w[k][q] = d_w[((size_t)b * Cq + c + q) * Kq + k] * g_inv_dnorm[b * Kq + k] * g;
    }
    __nv_bfloat16* oh = g_convhi + (size_t)b * Tq * Cq;
    __nv_bfloat16* ol = g_convlo + (size_t)b * Tq * Cq;
    #pragma unroll
    for (int i = 0; i < 4; ++i) {
        int tl = tsub * 4 + i;
        float4 acc = make_float4(bias[0], bias[1], bias[2], bias[3]);
        #pragma unroll
        for (int k = 0; k < Kq; ++k) {
            float4 vv = *(float4*)&s[tl + k][cg];
            acc.x = fmaf(vv.x, w[k][0], acc.x);
            acc.y = fmaf(vv.y, w[k][1], acc.y);
            acc.z = fmaf(vv.z, w[k][2], acc.z);
            acc.w = fmaf(vv.w, w[k][3], acc.w);
        }
        __nv_bfloat16 h0, h1, h2, h3, l0, l1, l2, l3;
        bsplit(acc.x, h0, l0); bsplit(acc.y, h1, l1);
        bsplit(acc.z, h2, l2); bsplit(acc.w, h3, l3);
        size_t off = (size_t)(t0 + tl) * Cq + c;
        *(__nv_bfloat162*)(oh + off)     = __nv_bfloat162{h0, h1};
        *(__nv_bfloat162*)(oh + off + 2) = __nv_bfloat162{h2, h3};
        *(__nv_bfloat162*)(ol + off)     = __nv_bfloat162{l0, l1};
        *(__nv_bfloat162*)(ol + off + 2) = __nv_bfloat162{l2, l3};
    }
}

// ===========================================================================
// mma.sync bf16-split GEMM. CTA tile 128x128, K-chunk 64, 3-stage cp.async.
// Smem tile: 128 rows x 128B data, pitch 144B (conflict-free ldmatrix).
// ===========================================================================
#define PITCH   144
#define TILE_B  (128 * PITCH)          // 18432
#define OFF_AH  0
#define OFF_AL  TILE_B
#define OFF_BH  (2 * TILE_B)
#define OFF_BL  (3 * TILE_B)
#define STAGE_B (4 * TILE_B)           // 73728
#define SMEM_ALLOC (3 * STAGE_B)       // 221184

__device__ __forceinline__ void load_tile(uint32_t dst, const __nv_bfloat16* src,
                                          int lda, int k0, int tid) {
    #pragma unroll
    for (int q = 0; q < 4; ++q) {
        int lin = tid + q * 256;
        int row = lin >> 3, seg = lin & 7;
        cp16(dst + (uint32_t)(row * PITCH + seg * 16),
             src + (size_t)row * lda + k0 + seg * 8);
    }
}
__device__ __forceinline__ void load_chunk(uint32_t st,
    const __nv_bfloat16* Ah, const __nv_bfloat16* Al,
    const __nv_bfloat16* Bh, const __nv_bfloat16* Bl,
    int lda, int ldb, int k0, int tid) {
    load_tile(st + OFF_AH, Ah, lda, k0, tid);
    load_tile(st + OFF_AL, Al, lda, k0, tid);
    load_tile(st + OFF_BH, Bh, ldb, k0, tid);
    load_tile(st + OFF_BL, Bl, ldb, k0, tid);
}

template <int EPI>
__global__ __launch_bounds__(256) void mma_gemm(
    const __nv_bfloat16* __restrict__ Ahi, const __nv_bfloat16* __restrict__ Alo,
    int lda, size_t astride,
    const __nv_bfloat16* __restrict__ Bhi, const __nv_bfloat16* __restrict__ Blo,
    int ldb, size_t bstride,
    int nchunks,
    const float* __restrict__ e0, const float* __restrict__ e1,
    float* __restrict__ out0) {
    extern __shared__ __align__(128) char dsm[];
    uint32_t sbase = smem_to_u32(dsm);
    int tid = threadIdx.x;
    int wid = tid >> 5, lane = tid & 31;
    int wm = wid >> 2, wn = wid & 3;          // warp grid 2(m) x 4(n)
    int b = blockIdx.z, m0 = blockIdx.y * 128, n0 = blockIdx.x * 128;

    const __nv_bfloat16* A_h = Ahi + (size_t)b * astride + (size_t)m0 * lda;
    const __nv_bfloat16* A_l = Alo + (size_t)b * astride + (size_t)m0 * lda;
    const __nv_bfloat16* B_h = Bhi + (size_t)b * bstride + (size_t)n0 * ldb;
    const __nv_bfloat16* B_l = Blo + (size_t)b * bstride + (size_t)n0 * ldb;

    // ldmatrix stage-relative offsets
    uint32_t a_off[4], b_off[4];
    {
        int arow = lane & 15;
        uint32_t ahalf = (lane & 16) ? 16u : 0u;
        #pragma unroll
        for (int i = 0; i < 4; ++i)
            a_off[i] = (uint32_t)((wm * 64 + i * 16 + arow) * PITCH) + ahalf;
        int l16 = lane & 15;
        int brow = l16 & 7;
        uint32_t bhalf = (l16 & 8) ? 16u : 0u;
        #pragma unroll
        for (int j = 0; j < 4; ++j)
            b_off[j] = (uint32_t)((wn * 32 + j * 8 + brow) * PITCH) + bhalf;
    }

    float acc[4][4][4] = {};

    load_chunk(sbase,               A_h, A_l, B_h, B_l, lda, ldb, 0, tid);
    CP_COMMIT();
    load_chunk(sbase + STAGE_B,     A_h, A_l, B_h, B_l, lda, ldb, 64, tid);
    CP_COMMIT();

    for (int j = 0; j < nchunks; ++j) {
        CP_WAIT1();
        __syncthreads();
        if (j + 2 < nchunks)
            load_chunk(sbase + (uint32_t)((j + 2) % 3) * STAGE_B,
                       A_h, A_l, B_h, B_l, lda, ldb, (j + 2) * 64, tid);
        CP_COMMIT();
        uint32_t st = sbase + (uint32_t)(j % 3) * STAGE_B;
        #pragma unroll
        for (int ks = 0; ks < 4; ++ks) {
            uint32_t koff = (uint32_t)(ks * 32);
            uint32_t ah[4][4], al[4][4], bh[4][2], bl[4][2];
            #pragma unroll
            for (int i = 0; i < 4; ++i) {
                LDSM_X4(ah[i], st + OFF_AH + a_off[i] + koff);
                LDSM_X4(al[i], st + OFF_AL + a_off[i] + koff);
            }
            #pragma unroll
            for (int jj = 0; jj < 4; ++jj) {
                LDSM_X2(bh[jj], st + OFF_BH + b_off[jj] + koff);
                LDSM_X2(bl[jj], st + OFF_BL + b_off[jj] + koff);
            }
            #pragma unroll
            for (int i = 0; i < 4; ++i)
                #pragma unroll
                for (int jj = 0; jj < 4; ++jj)
                    MMA_BF16(acc[i][jj], ah[i], bh[jj]);
            #pragma unroll
            for (int i = 0; i < 4; ++i)
                #pragma unroll
                for (int jj = 0; jj < 4; ++jj)
                    MMA_BF16(acc[i][jj], ah[i], bl[jj]);
            #pragma unroll
            for (int i = 0; i < 4; ++i)
                #pragma unroll
                for (int jj = 0; jj < 4; ++jj)
                    MMA_BF16(acc[i][jj], al[i], bh[jj]);
        }
    }

    // Epilogue: frag (i,jj): c0 (r, col), c1 (r, col+1), c2 (r+8, col), c3 (r+8, col+1)
    int gid = lane >> 2, tig = lane & 3;
    #pragma unroll
    for (int i = 0; i < 4; ++i) {
        int r0 = m0 + wm * 64 + i * 16 + gid;
        #pragma unroll
        for (int jj = 0; jj < 4; ++jj) {
            int col = n0 + wn * 32 + jj * 8 + tig * 2;
            float v0 = acc[i][jj][0], v1 = acc[i][jj][1];
            float v2 = acc[i][jj][2], v3 = acc[i][jj][3];
            if (EPI == 1) {
                float b0 = e0[col], b1v = e0[col + 1];
                float* d0 = g_hT + ((size_t)b * Tq + r0) * Cq + col;
                float* d1 = g_hT + ((size_t)b * Tq + r0 + 8) * Cq + col;
                *(float2*)d0 = float2{mishf(v0 + b0), mishf(v1 + b1v)};
                *(float2*)d1 = float2{mishf(v2 + b0), mishf(v3 + b1v)};
            } else if (EPI == 2) {
                float s0 = g_inv_pnorm[b * Cq + col], s1 = g_inv_pnorm[b * Cq + col + 1];
                float p0 = e0[b * Cq + col], p1 = e0[b * Cq + col + 1];
                float u0 = mishf(fmaf(v0, s0, p0)), u1 = mishf(fmaf(v1, s1, p1));
                float u2 = mishf(fmaf(v2, s0, p0)), u3 = mishf(fmaf(v3, s1, p1));
                __nv_bfloat16 h0, h1, h2, h3, l0, l1, l2, l3;
                bsplit(u0, h0, l0); bsplit(u1, h1, l1);
                bsplit(u2, h2, l2); bsplit(u3, h3, l3);
                size_t o0i = ((size_t)b * Tq + r0) * Cq + col;
                size_t o1i = ((size_t)b * Tq + r0 + 8) * Cq + col;
                *(__nv_bfloat162*)(g_tmphi + o0i) = __nv_bfloat162{h0, h1};
                *(__nv_bfloat162*)(g_tmphi + o1i) = __nv_bfloat162{h2, h3};
                *(__nv_bfloat162*)(g_tmplo + o0i) = __nv_bfloat162{l0, l1};
                *(__nv_bfloat162*)(g_tmplo + o1i) = __nv_bfloat162{l2, l3};
            } else {
                float b0 = e0[col], b1v = e0[col + 1];
                size_t o0i = ((size_t)b * Tq + r0) * Dq + col;
                size_t o1i = ((size_t)b * Tq + r0 + 8) * Dq + col;
                float2 x0 = *(const float2*)(e1 + o0i);
                float2 x1 = *(const float2*)(e1 + o1i);
                *(float2*)(out0 + o0i) = float2{v0 + b0 + x0.x, v1 + b1v + x0.y};
                *(float2*)(out0 + o1i) = float2{v2 + b0 + x1.x, v3 + b1v + x1.y};
            }
        }
    }
}

// ===========================================================================
extern "C" void kernel_launch(void* const* d_in, const int* in_sizes, int n_in,
                              void* d_out, int out_size) {
    const float* x   = (const float*)d_in[0];
    const float* d_w = (const float*)d_in[1];
    const float* d_g = (const float*)d_in[2];
    const float* d_b = (const float*)d_in[3];
    const float* p_w = (const float*)d_in[4];
    const float* p_g = (const float*)d_in[5];
    const float* p_b = (const float*)d_in[6];
    const float* w1  = (const float*)d_in[7];
    const float* b1  = (const float*)d_in[8];
    const float* w2  = (const float*)d_in[9];
    const float* b2  = (const float*)d_in[10];
    float* out = (float*)d_out;

    cudaFuncSetAttribute(mma_gemm<1>, cudaFuncAttributeMaxDynamicSharedMemorySize, SMEM_ALLOC);
    cudaFuncSetAttribute(mma_gemm<2>, cudaFuncAttributeMaxDynamicSharedMemorySize, SMEM_ALLOC);
    cudaFuncSetAttribute(mma_gemm<3>, cudaFuncAttributeMaxDynamicSharedMemorySize, SMEM_ALLOC);

    __nv_bfloat16 *xhi, *xlo, *w1hi, *w1lo, *w2hi, *w2lo;
    __nv_bfloat16 *convhi, *convlo, *pwhi, *pwlo, *tmphi, *tmplo;
    cudaGetSymbolAddress((void**)&xhi, g_xhi);
    cudaGetSymbolAddress((void**)&xlo, g_xlo);
    cudaGetSymbolAddress((void**)&w1hi, g_w1hi);
    cudaGetSymbolAddress((void**)&w1lo, g_w1lo);
    cudaGetSymbolAddress((void**)&w2hi, g_w2hi);
    cudaGetSymbolAddress((void**)&w2lo, g_w2lo);
    cudaGetSymbolAddress((void**)&convhi, g_convhi);
    cudaGetSymbolAddress((void**)&convlo, g_convlo);
    cudaGetSymbolAddress((void**)&pwhi, g_pwhi);
    cudaGetSymbolAddress((void**)&pwlo, g_pwlo);
    cudaGetSymbolAddress((void**)&tmphi, g_tmphi);
    cudaGetSymbolAddress((void**)&tmplo, g_tmplo);

    // prep
    split_kernel<<<(Bq * Tq * Dq / 4 + 255) / 256, 256>>>(x, xhi, xlo, Bq * Tq * Dq / 4);
    split_kernel<<<(Cq * Dq / 4 + 255) / 256, 256>>>(w1, w1hi, w1lo, Cq * Dq / 4);
    split_kernel<<<(Dq * Cq / 4 + 255) / 256, 256>>>(w2, w2hi, w2lo, Dq * Cq / 4);
    dnorm_kernel<<<Bq * Kq, 256>>>(d_w);
    pnorm_kernel<<<dim3(Bq, Cq / 256), 256>>>(p_w);
    pw_prep_kernel<<<dim3(Cq / 32, Cq / 32, Bq), 256>>>(p_w, p_g);

    // GEMM1: h[b,t,c] = mish(x @ w1^T + b1)
    mma_gemm<1><<<dim3(Cq / 128, Tq / 128, Bq), 256, SMEM_ALLOC>>>(
        xhi, xlo, Dq, (size_t)Tq * Dq,
        w1hi, w1lo, Dq, 0,
        Dq / 64, b1, nullptr, nullptr);

    // depthwise conv (on [t][c]) -> bf16 split
    conv_t_kernel<<<dim3(Cq / 512, Tq / 8, Bq), 256>>>(d_w, d_g, d_b);

    // GEMM2: tmp[b,t,o] = mish(inv_pnorm*(conv @ pw^T) + p_b)
    mma_gemm<2><<<dim3(Cq / 128, Tq / 128, Bq), 256, SMEM_ALLOC>>>(
        convhi, convlo, Cq, (size_t)Tq * Cq,
        pwhi, pwlo, Cq, (size_t)Cq * Cq,
        Cq / 64, p_b, nullptr, nullptr);

    // GEMM3: out[b,t,d] = tmp @ w2^T + b2 + x
    mma_gemm<3><<<dim3(Dq / 128, Tq / 128, Bq), 256, SMEM_ALLOC>>>(
        tmphi, tmplo, Cq, (size_t)Tq * Cq,
        w2hi, w2lo, Cq, 0,
        Cq / 64, b2, x, out);
}

// round 5
// speedup vs baseline: 1.8831x; 1.0412x over previous
#include <cuda_runtime.h>
#include <cuda_bf16.h>
#include <cstdint>
#include <math.h>

#define Bq  16
#define Tq  1024
#define Dq  256
#define Cq  1024
#define Kq  9

// ===========================================================================
// Helpers (baseline PTX only — no 'a'-suffix features)
// ===========================================================================
__device__ __forceinline__ uint32_t smem_to_u32(const void* p) {
    uint32_t a;
    asm("{ .reg .u64 t; cvta.to.shared.u64 t, %1; cvt.u32.u64 %0, t; }" : "=r"(a) : "l"(p));
    return a;
}
__device__ __forceinline__ void cp16(uint32_t sa, const void* g) {
    asm volatile("cp.async.cg.shared.global [%0], [%1], 16;\n" :: "r"(sa), "l"(g));
}
#define CP_COMMIT() asm volatile("cp.async.commit_group;\n" ::: "memory")
#define CP_WAIT1()  asm volatile("cp.async.wait_group 1;\n" ::: "memory")

#define LDSM_X4(r, a) \
    asm volatile("ldmatrix.sync.aligned.m8n8.x4.shared.b16 {%0,%1,%2,%3}, [%4];" \
        : "=r"((r)[0]), "=r"((r)[1]), "=r"((r)[2]), "=r"((r)[3]) : "r"(a))
#define LDSM_X2(r, a) \
    asm volatile("ldmatrix.sync.aligned.m8n8.x2.shared.b16 {%0,%1}, [%2];" \
        : "=r"((r)[0]), "=r"((r)[1]) : "r"(a))

#define MMA_BF16(d, a, bb) \
    asm volatile("mma.sync.aligned.m16n8k16.row.col.f32.bf16.bf16.f32 " \
        "{%0,%1,%2,%3}, {%4,%5,%6,%7}, {%8,%9}, {%0,%1,%2,%3};" \
        : "+f"((d)[0]), "+f"((d)[1]), "+f"((d)[2]), "+f"((d)[3]) \
        : "r"((a)[0]), "r"((a)[1]), "r"((a)[2]), "r"((a)[3]), \
          "r"((bb)[0]), "r"((bb)[1]))

// mish(x) = x * tanh(softplus(x)) = x * w / (w + 2),  w = e^x (e^x + 2).
// One MUFU exp + fast divide. x>15 -> x (tail < 1e-12); x->-inf -> 0, no
// cancellation (w computed from e^x directly).
__device__ __forceinline__ float mishf(float x) {
    if (x > 15.f) return x;
    float t = __expf(x);
    float w = t * (t + 2.f);
    return x * __fdividef(w, w + 2.f);
}
__device__ __forceinline__ void bsplit(float v, __nv_bfloat16& h, __nv_bfloat16& l) {
    h = __float2bfloat16(v);
    l = __float2bfloat16(v - __bfloat162float(h));
}

// ===========================================================================
// Device scratch (bf16 split operands; fp32 intermediates)
// ===========================================================================
__device__ __align__(16) __nv_bfloat16 g_xhi[(size_t)Bq * Tq * Dq];
__device__ __align__(16) __nv_bfloat16 g_xlo[(size_t)Bq * Tq * Dq];
__device__ __align__(16) __nv_bfloat16 g_w1hi[(size_t)Cq * Dq];
__device__ __align__(16) __nv_bfloat16 g_w1lo[(size_t)Cq * Dq];
__device__ __align__(16) __nv_bfloat16 g_w2hi[(size_t)Dq * Cq];
__device__ __align__(16) __nv_bfloat16 g_w2lo[(size_t)Dq * Cq];
__device__ __align__(16) float g_hT[(size_t)Bq * Tq * Cq];              // [b][t][c]
__device__ __align__(16) __nv_bfloat16 g_convhi[(size_t)Bq * Tq * Cq];  // [b][t][c]
__device__ __align__(16) __nv_bfloat16 g_convlo[(size_t)Bq * Tq * Cq];
__device__ __align__(16) __nv_bfloat16 g_pwhi[(size_t)Bq * Cq * Cq];    // [b][o][c]
__device__ __align__(16) __nv_bfloat16 g_pwlo[(size_t)Bq * Cq * Cq];
__device__ __align__(16) __nv_bfloat16 g_tmphi[(size_t)Bq * Tq * Cq];   // [b][t][o]
__device__ __align__(16) __nv_bfloat16 g_tmplo[(size_t)Bq * Tq * Cq];
__device__ float g_inv_pnorm[Bq * Cq];
__device__ float g_inv_dnorm[Bq * Kq];

// ===========================================================================
// Prep kernels
// ===========================================================================
__global__ void split_kernel(const float* __restrict__ src,
                             __nv_bfloat16* __restrict__ hi,
                             __nv_bfloat16* __restrict__ lo, int n4) {
    int i = blockIdx.x * 256 + threadIdx.x;
    if (i >= n4) return;
    float4 v = ((const float4*)src)[i];
    __nv_bfloat16 h0, h1, h2, h3, l0, l1, l2, l3;
    bsplit(v.x, h0, l0); bsplit(v.y, h1, l1);
    bsplit(v.z, h2, l2); bsplit(v.w, h3, l3);
    ((__nv_bfloat162*)hi)[2 * i]     = __nv_bfloat162{h0, h1};
    ((__nv_bfloat162*)hi)[2 * i + 1] = __nv_bfloat162{h2, h3};
    ((__nv_bfloat162*)lo)[2 * i]     = __nv_bfloat162{l0, l1};
    ((__nv_bfloat162*)lo)[2 * i + 1] = __nv_bfloat162{l2, l3};
}

__global__ void dnorm_kernel(const float* __restrict__ d_w) {
    int bk = blockIdx.x;
    int b = bk / Kq, k = bk % Kq;
    float s = 0.f;
    for (int c = threadIdx.x; c < Cq; c += 256) {
        float v = d_w[((size_t)b * Cq + c) * Kq + k];
        s = fmaf(v, v, s);
    }
    __shared__ float red[256];
    red[threadIdx.x] = s;
    __syncthreads();
    for (int off = 128; off > 0; off >>= 1) {
        if (threadIdx.x < off) red[threadIdx.x] += red[threadIdx.x + off];
        __syncthreads();
    }
    if (threadIdx.x == 0)
        g_inv_dnorm[bk] = 1.f / fmaxf(sqrtf(red[0]), 1e-12f);
}

__global__ void pnorm_kernel(const float* __restrict__ p_w) {
    int b = blockIdx.x;
    int o = blockIdx.y * 256 + threadIdx.x;
    const float* base = p_w + (size_t)b * Cq * Cq + o;
    float s = 0.f;
    #pragma unroll 4
    for (int c = 0; c < Cq; ++c) {
        float v = base[(size_t)c * Cq];
        s = fmaf(v, v, s);
    }
    g_inv_pnorm[b * Cq + o] = 1.f / fmaxf(sqrtf(s), 1e-12f);
}

// Transpose p_w[b][c][o]*p_g[b][c] -> [b][o][c], bf16 split.
__global__ __launch_bounds__(256) void pw_prep_kernel(
    const float* __restrict__ p_w, const float* __restrict__ p_g) {
    int b = blockIdx.z;
    int c0 = blockIdx.x * 32;
    int o0 = blockIdx.y * 32;
    __shared__ float s[32][33];
    __shared__ float pgs[32];
    int tid = threadIdx.x;
    int x = tid & 31, y = tid >> 5;
    if (tid < 32) pgs[tid] = p_g[b * Cq + c0 + tid];
    const float* in = p_w + (size_t)b * Cq * Cq;
    #pragma unroll
    for (int yy = 0; yy < 4; ++yy) {
        int c = c0 + y * 4 + yy;
        s[y * 4 + yy][x] = in[(size_t)c * Cq + o0 + x];
    }
    __syncthreads();
    __nv_bfloat16* ohi = g_pwhi + (size_t)b * Cq * Cq;
    __nv_bfloat16* olo = g_pwlo + (size_t)b * Cq * Cq;
    #pragma unroll
    for (int yy = 0; yy < 4; ++yy) {
        int o = o0 + y * 4 + yy;
        float w = s[x][y * 4 + yy] * pgs[x];
        __nv_bfloat16 h, l;
        bsplit(w, h, l);
        ohi[(size_t)o * Cq + c0 + x] = h;
        olo[(size_t)o * Cq + c0 + x] = l;
    }
}

// ===========================================================================
// Depthwise conv on [t][c] layout -> bf16 split
// ===========================================================================
__global__ __launch_bounds__(256) void conv_t_kernel(
    const float* __restrict__ d_w, const float* __restrict__ d_g,
    const float* __restrict__ d_b) {
    int b  = blockIdx.z;
    int t0 = blockIdx.y * 8;
    int ch = blockIdx.x * 512;
    __shared__ float s[16][512];
    const float* h = g_hT + (size_t)b * Tq * Cq;
    int tid = threadIdx.x;
    #pragma unroll
    for (int i = 0; i < 8; ++i) {
        int idx = tid + i * 256;
        int r  = idx >> 7;
        int cc = (idx & 127) * 4;
        int t = t0 - 4 + r;
        float4 v = (t >= 0 && t < Tq)
            ? *(const float4*)(h + (size_t)t * Cq + ch + cc)
            : make_float4(0.f, 0.f, 0.f, 0.f);
        *(float4*)&s[r][cc] = v;
    }
    __syncthreads();
    int cg = (tid & 127) * 4;
    int tsub = tid >> 7;
    int c = ch + cg;
    float w[Kq][4], bias[4];
    #pragma unroll
    for (int q = 0; q < 4; ++q) {
        float g = d_g[b * Cq + c + q];
        bias[q] = d_b[b * Cq + c + q];
        #pragma unroll
        for (int k = 0; k < Kq; ++k)
            w[k][q] = d_w[((size_t)b * Cq + c + q) * Kq + k] * g_inv_dnorm[b * Kq + k] * g;
    }
    __nv_bfloat16* oh = g_convhi + (size_t)b * Tq * Cq;
    __nv_bfloat16* ol = g_convlo + (size_t)b * Tq * Cq;
    #pragma unroll
    for (int i = 0; i < 4; ++i) {
        int tl = tsub * 4 + i;
        float4 acc = make_float4(bias[0], bias[1], bias[2], bias[3]);
        #pragma unroll
        for (int k = 0; k < Kq; ++k) {
            float4 vv = *(float4*)&s[tl + k][cg];
            acc.x = fmaf(vv.x, w[k][0], acc.x);
            acc.y = fmaf(vv.y, w[k][1], acc.y);
            acc.z = fmaf(vv.z, w[k][2], acc.z);
            acc.w = fmaf(vv.w, w[k][3], acc.w);
        }
        __nv_bfloat16 h0, h1, h2, h3, l0, l1, l2, l3;
        bsplit(acc.x, h0, l0); bsplit(acc.y, h1, l1);
        bsplit(acc.z, h2, l2); bsplit(acc.w, h3, l3);
        size_t off = (size_t)(t0 + tl) * Cq + c;
        *(__nv_bfloat162*)(oh + off)     = __nv_bfloat162{h0, h1};
        *(__nv_bfloat162*)(oh + off + 2) = __nv_bfloat162{h2, h3};
        *(__nv_bfloat162*)(ol + off)     = __nv_bfloat162{l0, l1};
        *(__nv_bfloat162*)(ol + off + 2) = __nv_bfloat162{l2, l3};
    }
}

// ===========================================================================
// mma.sync bf16-split GEMM. CTA tile 128x128, K-chunk 64, 3-stage cp.async.
// Smem tile: 128 rows x 128B data, pitch 144B (conflict-free ldmatrix).
// ===========================================================================
#define PITCH   144
#define TILE_B  (128 * PITCH)          // 18432
#define OFF_AH  0
#define OFF_AL  TILE_B
#define OFF_BH  (2 * TILE_B)
#define OFF_BL  (3 * TILE_B)
#define STAGE_B (4 * TILE_B)           // 73728
#define SMEM_ALLOC (3 * STAGE_B)       // 221184

__device__ __forceinline__ void load_tile(uint32_t dst, const __nv_bfloat16* src,
                                          int lda, int k0, int tid) {
    #pragma unroll
    for (int q = 0; q < 4; ++q) {
        int lin = tid + q * 256;
        int row = lin >> 3, seg = lin & 7;
        cp16(dst + (uint32_t)(row * PITCH + seg * 16),
             src + (size_t)row * lda + k0 + seg * 8);
    }
}
__device__ __forceinline__ void load_chunk(uint32_t st,
    const __nv_bfloat16* Ah, const __nv_bfloat16* Al,
    const __nv_bfloat16* Bh, const __nv_bfloat16* Bl,
    int lda, int ldb, int k0, int tid) {
    load_tile(st + OFF_AH, Ah, lda, k0, tid);
    load_tile(st + OFF_AL, Al, lda, k0, tid);
    load_tile(st + OFF_BH, Bh, ldb, k0, tid);
    load_tile(st + OFF_BL, Bl, ldb, k0, tid);
}

template <int EPI>
__global__ __launch_bounds__(256) void mma_gemm(
    const __nv_bfloat16* __restrict__ Ahi, const __nv_bfloat16* __restrict__ Alo,
    int lda, size_t astride,
    const __nv_bfloat16* __restrict__ Bhi, const __nv_bfloat16* __restrict__ Blo,
    int ldb, size_t bstride,
    int nchunks,
    const float* __restrict__ e0, const float* __restrict__ e1,
    float* __restrict__ out0) {
    extern __shared__ __align__(128) char dsm[];
    uint32_t sbase = smem_to_u32(dsm);
    int tid = threadIdx.x;
    int wid = tid >> 5, lane = tid & 31;
    int wm = wid >> 2, wn = wid & 3;          // warp grid 2(m) x 4(n)
    int b = blockIdx.z, m0 = blockIdx.y * 128, n0 = blockIdx.x * 128;

    const __nv_bfloat16* A_h = Ahi + (size_t)b * astride + (size_t)m0 * lda;
    const __nv_bfloat16* A_l = Alo + (size_t)b * astride + (size_t)m0 * lda;
    const __nv_bfloat16* B_h = Bhi + (size_t)b * bstride + (size_t)n0 * ldb;
    const __nv_bfloat16* B_l = Blo + (size_t)b * bstride + (size_t)n0 * ldb;

    // ldmatrix stage-relative offsets
    uint32_t a_off[4], b_off[4];
    {
        int arow = lane & 15;
        uint32_t ahalf = (lane & 16) ? 16u : 0u;
        #pragma unroll
        for (int i = 0; i < 4; ++i)
            a_off[i] = (uint32_t)((wm * 64 + i * 16 + arow) * PITCH) + ahalf;
        int l16 = lane & 15;
        int brow = l16 & 7;
        uint32_t bhalf = (l16 & 8) ? 16u : 0u;
        #pragma unroll
        for (int j = 0; j < 4; ++j)
            b_off[j] = (uint32_t)((wn * 32 + j * 8 + brow) * PITCH) + bhalf;
    }

    float acc[4][4][4] = {};

    load_chunk(sbase,               A_h, A_l, B_h, B_l, lda, ldb, 0, tid);
    CP_COMMIT();
    load_chunk(sbase + STAGE_B,     A_h, A_l, B_h, B_l, lda, ldb, 64, tid);
    CP_COMMIT();

    for (int j = 0; j < nchunks; ++j) {
        CP_WAIT1();
        __syncthreads();
        if (j + 2 < nchunks)
            load_chunk(sbase + (uint32_t)((j + 2) % 3) * STAGE_B,
                       A_h, A_l, B_h, B_l, lda, ldb, (j + 2) * 64, tid);
        CP_COMMIT();
        uint32_t st = sbase + (uint32_t)(j % 3) * STAGE_B;
        #pragma unroll
        for (int ks = 0; ks < 4; ++ks) {
            uint32_t koff = (uint32_t)(ks * 32);
            uint32_t ah[4][4], al[4][4], bh[4][2], bl[4][2];
            #pragma unroll
            for (int i = 0; i < 4; ++i) {
                LDSM_X4(ah[i], st + OFF_AH + a_off[i] + koff);
                LDSM_X4(al[i], st + OFF_AL + a_off[i] + koff);
            }
            #pragma unroll
            for (int jj = 0; jj < 4; ++jj) {
                LDSM_X2(bh[jj], st + OFF_BH + b_off[jj] + koff);
                LDSM_X2(bl[jj], st + OFF_BL + b_off[jj] + koff);
            }
            #pragma unroll
            for (int i = 0; i < 4; ++i)
                #pragma unroll
                for (int jj = 0; jj < 4; ++jj)
                    MMA_BF16(acc[i][jj], ah[i], bh[jj]);
            #pragma unroll
            for (int i = 0; i < 4; ++i)
                #pragma unroll
                for (int jj = 0; jj < 4; ++jj)
                    MMA_BF16(acc[i][jj], ah[i], bl[jj]);
            #pragma unroll
            for (int i = 0; i < 4; ++i)
                #pragma unroll
                for (int jj = 0; jj < 4; ++jj)
                    MMA_BF16(acc[i][jj], al[i], bh[jj]);
        }
    }

    // Epilogue: frag (i,jj): c0 (r, col), c1 (r, col+1), c2 (r+8, col), c3 (r+8, col+1)
    int gid = lane >> 2, tig = lane & 3;
    #pragma unroll
    for (int i = 0; i < 4; ++i) {
        int r0 = m0 + wm * 64 + i * 16 + gid;
        #pragma unroll
        for (int jj = 0; jj < 4; ++jj) {
            int col = n0 + wn * 32 + jj * 8 + tig * 2;
            float v0 = acc[i][jj][0], v1 = acc[i][jj][1];
            float v2 = acc[i][jj][2], v3 = acc[i][jj][3];
            if (EPI == 1) {
                float b0 = e0[col], b1v = e0[col + 1];
                float* d0 = g_hT + ((size_t)b * Tq + r0) * Cq + col;
                float* d1 = g_hT + ((size_t)b * Tq + r0 + 8) * Cq + col;
                *(float2*)d0 = float2{mishf(v0 + b0), mishf(v1 + b1v)};
                *(float2*)d1 = float2{mishf(v2 + b0), mishf(v3 + b1v)};
            } else if (EPI == 2) {
                float s0 = g_inv_pnorm[b * Cq + col], s1 = g_inv_pnorm[b * Cq + col + 1];
                float p0 = e0[b * Cq + col], p1 = e0[b * Cq + col + 1];
                float u0 = mishf(fmaf(v0, s0, p0)), u1 = mishf(fmaf(v1, s1, p1));
                float u2 = mishf(fmaf(v2, s0, p0)), u3 = mishf(fmaf(v3, s1, p1));
                __nv_bfloat16 h0, h1, h2, h3, l0, l1, l2, l3;
                bsplit(u0, h0, l0); bsplit(u1, h1, l1);
                bsplit(u2, h2, l2); bsplit(u3, h3, l3);
                size_t o0i = ((size_t)b * Tq + r0) * Cq + col;
                size_t o1i = ((size_t)b * Tq + r0 + 8) * Cq + col;
                *(__nv_bfloat162*)(g_tmphi + o0i) = __nv_bfloat162{h0, h1};
                *(__nv_bfloat162*)(g_tmphi + o1i) = __nv_bfloat162{h2, h3};
                *(__nv_bfloat162*)(g_tmplo + o0i) = __nv_bfloat162{l0, l1};
                *(__nv_bfloat162*)(g_tmplo + o1i) = __nv_bfloat162{l2, l3};
            } else {
                float b0 = e0[col], b1v = e0[col + 1];
                size_t o0i = ((size_t)b * Tq + r0) * Dq + col;
                size_t o1i = ((size_t)b * Tq + r0 + 8) * Dq + col;
                float2 x0 = *(const float2*)(e1 + o0i);
                float2 x1 = *(const float2*)(e1 + o1i);
                *(float2*)(out0 + o0i) = float2{v0 + b0 + x0.x, v1 + b1v + x0.y};
                *(float2*)(out0 + o1i) = float2{v2 + b0 + x1.x, v3 + b1v + x1.y};
            }
        }
    }
}

// ===========================================================================
extern "C" void kernel_launch(void* const* d_in, const int* in_sizes, int n_in,
                              void* d_out, int out_size) {
    const float* x   = (const float*)d_in[0];
    const float* d_w = (const float*)d_in[1];
    const float* d_g = (const float*)d_in[2];
    const float* d_b = (const float*)d_in[3];
    const float* p_w = (const float*)d_in[4];
    const float* p_g = (const float*)d_in[5];
    const float* p_b = (const float*)d_in[6];
    const float* w1  = (const float*)d_in[7];
    const float* b1  = (const float*)d_in[8];
    const float* w2  = (const float*)d_in[9];
    const float* b2  = (const float*)d_in[10];
    float* out = (float*)d_out;

    cudaFuncSetAttribute(mma_gemm<1>, cudaFuncAttributeMaxDynamicSharedMemorySize, SMEM_ALLOC);
    cudaFuncSetAttribute(mma_gemm<2>, cudaFuncAttributeMaxDynamicSharedMemorySize, SMEM_ALLOC);
    cudaFuncSetAttribute(mma_gemm<3>, cudaFuncAttributeMaxDynamicSharedMemorySize, SMEM_ALLOC);

    __nv_bfloat16 *xhi, *xlo, *w1hi, *w1lo, *w2hi, *w2lo;
    __nv_bfloat16 *convhi, *convlo, *pwhi, *pwlo, *tmphi, *tmplo;
    cudaGetSymbolAddress((void**)&xhi, g_xhi);
    cudaGetSymbolAddress((void**)&xlo, g_xlo);
    cudaGetSymbolAddress((void**)&w1hi, g_w1hi);
    cudaGetSymbolAddress((void**)&w1lo, g_w1lo);
    cudaGetSymbolAddress((void**)&w2hi, g_w2hi);
    cudaGetSymbolAddress((void**)&w2lo, g_w2lo);
    cudaGetSymbolAddress((void**)&convhi, g_convhi);
    cudaGetSymbolAddress((void**)&convlo, g_convlo);
    cudaGetSymbolAddress((void**)&pwhi, g_pwhi);
    cudaGetSymbolAddress((void**)&pwlo, g_pwlo);
    cudaGetSymbolAddress((void**)&tmphi, g_tmphi);
    cudaGetSymbolAddress((void**)&tmplo, g_tmplo);

    // Launch order: gemm1 at index 3 so ncu (which captures launch #3) profiles it.
    split_kernel<<<(Bq * Tq * Dq / 4 + 255) / 256, 256>>>(x, xhi, xlo, Bq * Tq * Dq / 4);
    split_kernel<<<(Cq * Dq / 4 + 255) / 256, 256>>>(w1, w1hi, w1lo, Cq * Dq / 4);
    split_kernel<<<(Dq * Cq / 4 + 255) / 256, 256>>>(w2, w2hi, w2lo, Dq * Cq / 4);

    // GEMM1: h[b,t,c] = mish(x @ w1^T + b1)
    mma_gemm<1><<<dim3(Cq / 128, Tq / 128, Bq), 256, SMEM_ALLOC>>>(
        xhi, xlo, Dq, (size_t)Tq * Dq,
        w1hi, w1lo, Dq, 0,
        Dq / 64, b1, nullptr, nullptr);

    dnorm_kernel<<<Bq * Kq, 256>>>(d_w);
    pnorm_kernel<<<dim3(Bq, Cq / 256), 256>>>(p_w);
    pw_prep_kernel<<<dim3(Cq / 32, Cq / 32, Bq), 256>>>(p_w, p_g);

    // depthwise conv (on [t][c]) -> bf16 split
    conv_t_kernel<<<dim3(Cq / 512, Tq / 8, Bq), 256>>>(d_w, d_g, d_b);

    // GEMM2: tmp[b,t,o] = mish(inv_pnorm*(conv @ pw^T) + p_b)
    mma_gemm<2><<<dim3(Cq / 128, Tq / 128, Bq), 256, SMEM_ALLOC>>>(
        convhi, convlo, Cq, (size_t)Tq * Cq,
        pwhi, pwlo, Cq, (size_t)Cq * Cq,
        Cq / 64, p_b, nullptr, nullptr);

    // GEMM3: out[b,t,d] = tmp @ w2^T + b2 + x
    mma_gemm<3><<<dim3(Dq / 128, Tq / 128, Bq), 256, SMEM_ALLOC>>>(
        tmphi, tmplo, Cq, (size_t)Tq * Cq,
        w2hi, w2lo, Cq, 0,
        Cq / 64, b2, x, out);
}

// round 6
// speedup vs baseline: 1.9810x; 1.0520x over previous
#include <cuda_runtime.h>
#include <cuda_bf16.h>
#include <cstdint>
#include <math.h>

#define Bq  16
#define Tq  1024
#define Dq  256
#define Cq  1024
#define Kq  9

// ===========================================================================
// Helpers (baseline PTX only — no 'a'-suffix features)
// ===========================================================================
__device__ __forceinline__ uint32_t smem_to_u32(const void* p) {
    uint32_t a;
    asm("{ .reg .u64 t; cvta.to.shared.u64 t, %1; cvt.u32.u64 %0, t; }" : "=r"(a) : "l"(p));
    return a;
}
__device__ __forceinline__ void cp16(uint32_t sa, const void* g) {
    asm volatile("cp.async.cg.shared.global [%0], [%1], 16;\n" :: "r"(sa), "l"(g));
}
#define CP_COMMIT() asm volatile("cp.async.commit_group;\n" ::: "memory")
#define CP_WAIT(n)  asm volatile("cp.async.wait_group %0;\n" :: "n"(n) : "memory")

#define LDSM_X4(r, a) \
    asm volatile("ldmatrix.sync.aligned.m8n8.x4.shared.b16 {%0,%1,%2,%3}, [%4];" \
        : "=r"((r)[0]), "=r"((r)[1]), "=r"((r)[2]), "=r"((r)[3]) : "r"(a))
#define LDSM_X2(r, a) \
    asm volatile("ldmatrix.sync.aligned.m8n8.x2.shared.b16 {%0,%1}, [%2];" \
        : "=r"((r)[0]), "=r"((r)[1]) : "r"(a))

#define MMA_BF16(d, a, bb) \
    asm volatile("mma.sync.aligned.m16n8k16.row.col.f32.bf16.bf16.f32 " \
        "{%0,%1,%2,%3}, {%4,%5,%6,%7}, {%8,%9}, {%0,%1,%2,%3};" \
        : "+f"((d)[0]), "+f"((d)[1]), "+f"((d)[2]), "+f"((d)[3]) \
        : "r"((a)[0]), "r"((a)[1]), "r"((a)[2]), "r"((a)[3]), \
          "r"((bb)[0]), "r"((bb)[1]))

// mish(x) = x * w / (w + 2),  w = e^x (e^x + 2)
__device__ __forceinline__ float mishf(float x) {
    if (x > 15.f) return x;
    float t = __expf(x);
    float w = t * (t + 2.f);
    return x * __fdividef(w, w + 2.f);
}
__device__ __forceinline__ void bsplit(float v, __nv_bfloat16& h, __nv_bfloat16& l) {
    h = __float2bfloat16(v);
    l = __float2bfloat16(v - __bfloat162float(h));
}

// ===========================================================================
// Device scratch
// ===========================================================================
__device__ __align__(16) __nv_bfloat16 g_xhi[(size_t)Bq * Tq * Dq];
__device__ __align__(16) __nv_bfloat16 g_xlo[(size_t)Bq * Tq * Dq];
__device__ __align__(16) __nv_bfloat16 g_w1hi[(size_t)Cq * Dq];
__device__ __align__(16) __nv_bfloat16 g_w1lo[(size_t)Cq * Dq];
__device__ __align__(16) __nv_bfloat16 g_w2hi[(size_t)Dq * Cq];
__device__ __align__(16) __nv_bfloat16 g_w2lo[(size_t)Dq * Cq];
__device__ __align__(16) float g_hT[(size_t)Bq * Tq * Cq];              // [b][t][c]
__device__ __align__(16) __nv_bfloat16 g_convhi[(size_t)Bq * Tq * Cq];  // [b][t][c]
__device__ __align__(16) __nv_bfloat16 g_convlo[(size_t)Bq * Tq * Cq];
__device__ __align__(16) __nv_bfloat16 g_pwhi[(size_t)Bq * Cq * Cq];    // [b][o][c]
__device__ __align__(16) __nv_bfloat16 g_pwlo[(size_t)Bq * Cq * Cq];
__device__ __align__(16) __nv_bfloat16 g_tmphi[(size_t)Bq * Tq * Cq];   // [b][t][o]
__device__ __align__(16) __nv_bfloat16 g_tmplo[(size_t)Bq * Tq * Cq];
__device__ float g_inv_pnorm[Bq * Cq];
__device__ float g_inv_dnorm[Bq * Kq];

// ===========================================================================
// Prep kernels
// ===========================================================================
__global__ void split_kernel(const float* __restrict__ src,
                             __nv_bfloat16* __restrict__ hi,
                             __nv_bfloat16* __restrict__ lo, int n4) {
    int i = blockIdx.x * 256 + threadIdx.x;
    if (i >= n4) return;
    float4 v = ((const float4*)src)[i];
    __nv_bfloat16 h0, h1, h2, h3, l0, l1, l2, l3;
    bsplit(v.x, h0, l0); bsplit(v.y, h1, l1);
    bsplit(v.z, h2, l2); bsplit(v.w, h3, l3);
    ((__nv_bfloat162*)hi)[2 * i]     = __nv_bfloat162{h0, h1};
    ((__nv_bfloat162*)hi)[2 * i + 1] = __nv_bfloat162{h2, h3};
    ((__nv_bfloat162*)lo)[2 * i]     = __nv_bfloat162{l0, l1};
    ((__nv_bfloat162*)lo)[2 * i + 1] = __nv_bfloat162{l2, l3};
}

__global__ void dnorm_kernel(const float* __restrict__ d_w) {
    int bk = blockIdx.x;
    int b = bk / Kq, k = bk % Kq;
    float s = 0.f;
    for (int c = threadIdx.x; c < Cq; c += 256) {
        float v = d_w[((size_t)b * Cq + c) * Kq + k];
        s = fmaf(v, v, s);
    }
    __shared__ float red[256];
    red[threadIdx.x] = s;
    __syncthreads();
    for (int off = 128; off > 0; off >>= 1) {
        if (threadIdx.x < off) red[threadIdx.x] += red[threadIdx.x + off];
        __syncthreads();
    }
    if (threadIdx.x == 0)
        g_inv_dnorm[bk] = 1.f / fmaxf(sqrtf(red[0]), 1e-12f);
}

__global__ void pnorm_kernel(const float* __restrict__ p_w) {
    int b = blockIdx.x;
    int o = blockIdx.y * 256 + threadIdx.x;
    const float* base = p_w + (size_t)b * Cq * Cq + o;
    float s = 0.f;
    #pragma unroll 4
    for (int c = 0; c < Cq; ++c) {
        float v = base[(size_t)c * Cq];
        s = fmaf(v, v, s);
    }
    g_inv_pnorm[b * Cq + o] = 1.f / fmaxf(sqrtf(s), 1e-12f);
}

// Transpose p_w[b][c][o]*p_g[b][c] -> [b][o][c], bf16 split.
__global__ __launch_bounds__(256) void pw_prep_kernel(
    const float* __restrict__ p_w, const float* __restrict__ p_g) {
    int b = blockIdx.z;
    int c0 = blockIdx.x * 32;
    int o0 = blockIdx.y * 32;
    __shared__ float s[32][33];
    __shared__ float pgs[32];
    int tid = threadIdx.x;
    int x = tid & 31, y = tid >> 5;
    if (tid < 32) pgs[tid] = p_g[b * Cq + c0 + tid];
    const float* in = p_w + (size_t)b * Cq * Cq;
    #pragma unroll
    for (int yy = 0; yy < 4; ++yy) {
        int c = c0 + y * 4 + yy;
        s[y * 4 + yy][x] = in[(size_t)c * Cq + o0 + x];
    }
    __syncthreads();
    __nv_bfloat16* ohi = g_pwhi + (size_t)b * Cq * Cq;
    __nv_bfloat16* olo = g_pwlo + (size_t)b * Cq * Cq;
    #pragma unroll
    for (int yy = 0; yy < 4; ++yy) {
        int o = o0 + y * 4 + yy;
        float w = s[x][y * 4 + yy] * pgs[x];
        __nv_bfloat16 h, l;
        bsplit(w, h, l);
        ohi[(size_t)o * Cq + c0 + x] = h;
        olo[(size_t)o * Cq + c0 + x] = l;
    }
}

// ===========================================================================
// Depthwise conv on [t][c] layout -> bf16 split
// ===========================================================================
__global__ __launch_bounds__(256) void conv_t_kernel(
    const float* __restrict__ d_w, const float* __restrict__ d_g,
    const float* __restrict__ d_b) {
    int b  = blockIdx.z;
    int t0 = blockIdx.y * 8;
    int ch = blockIdx.x * 512;
    __shared__ float s[16][512];
    const float* h = g_hT + (size_t)b * Tq * Cq;
    int tid = threadIdx.x;
    #pragma unroll
    for (int i = 0; i < 8; ++i) {
        int idx = tid + i * 256;
        int r  = idx >> 7;
        int cc = (idx & 127) * 4;
        int t = t0 - 4 + r;
        float4 v = (t >= 0 && t < Tq)
            ? *(const float4*)(h + (size_t)t * Cq + ch + cc)
            : make_float4(0.f, 0.f, 0.f, 0.f);
        *(float4*)&s[r][cc] = v;
    }
    __syncthreads();
    int cg = (tid & 127) * 4;
    int tsub = tid >> 7;
    int c = ch + cg;
    float w[Kq][4], bias[4];
    #pragma unroll
    for (int q = 0; q < 4; ++q) {
        float g = d_g[b * Cq + c + q];
        bias[q] = d_b[b * Cq + c + q];
        #pragma unroll
        for (int k = 0; k < Kq; ++k)
            w[k][q] = d_w[((size_t)b * Cq + c + q) * Kq + k] * g_inv_dnorm[b * Kq + k] * g;
    }
    __nv_bfloat16* oh = g_convhi + (size_t)b * Tq * Cq;
    __nv_bfloat16* ol = g_convlo + (size_t)b * Tq * Cq;
    #pragma unroll
    for (int i = 0; i < 4; ++i) {
        int tl = tsub * 4 + i;
        float4 acc = make_float4(bias[0], bias[1], bias[2], bias[3]);
        #pragma unroll
        for (int k = 0; k < Kq; ++k) {
            float4 vv = *(float4*)&s[tl + k][cg];
            acc.x = fmaf(vv.x, w[k][0], acc.x);
            acc.y = fmaf(vv.y, w[k][1], acc.y);
            acc.z = fmaf(vv.z, w[k][2], acc.z);
            acc.w = fmaf(vv.w, w[k][3], acc.w);
        }
        __nv_bfloat16 h0, h1, h2, h3, l0, l1, l2, l3;
        bsplit(acc.x, h0, l0); bsplit(acc.y, h1, l1);
        bsplit(acc.z, h2, l2); bsplit(acc.w, h3, l3);
        size_t off = (size_t)(t0 + tl) * Cq + c;
        *(__nv_bfloat162*)(oh + off)     = __nv_bfloat162{h0, h1};
        *(__nv_bfloat162*)(oh + off + 2) = __nv_bfloat162{h2, h3};
        *(__nv_bfloat162*)(ol + off)     = __nv_bfloat162{l0, l1};
        *(__nv_bfloat162*)(ol + off + 2) = __nv_bfloat162{l2, l3};
    }
}

// ===========================================================================
// mma.sync bf16-split GEMM. CTA tile 128x128, K-chunk 32, 2-stage cp.async.
// Smem tile: 128 rows x 64B data, pitch 80B (conflict-free ldmatrix).
// 80KB smem/CTA -> 2 CTAs/SM -> 4 warps/SMSP (latency hiding).
// ===========================================================================
#define PITCH   80
#define TILE_B  (128 * PITCH)          // 10240
#define OFF_AH  0
#define OFF_AL  TILE_B
#define OFF_BH  (2 * TILE_B)
#define OFF_BL  (3 * TILE_B)
#define STAGE_B (4 * TILE_B)           // 40960
#define SMEM_ALLOC (2 * STAGE_B)       // 81920

__device__ __forceinline__ void load_tile(uint32_t dst, const __nv_bfloat16* src,
                                          int lda, int k0, int tid) {
    #pragma unroll
    for (int q = 0; q < 2; ++q) {
        int lin = tid + q * 256;       // 0..511
        int row = lin >> 2, seg = lin & 3;
        cp16(dst + (uint32_t)(row * PITCH + seg * 16),
             src + (size_t)row * lda + k0 + seg * 8);
    }
}
__device__ __forceinline__ void load_chunk(uint32_t st,
    const __nv_bfloat16* Ah, const __nv_bfloat16* Al,
    const __nv_bfloat16* Bh, const __nv_bfloat16* Bl,
    int lda, int ldb, int k0, int tid) {
    load_tile(st + OFF_AH, Ah, lda, k0, tid);
    load_tile(st + OFF_AL, Al, lda, k0, tid);
    load_tile(st + OFF_BH, Bh, ldb, k0, tid);
    load_tile(st + OFF_BL, Bl, ldb, k0, tid);
}

template <int EPI>
__global__ __launch_bounds__(256, 2) void mma_gemm(
    const __nv_bfloat16* __restrict__ Ahi, const __nv_bfloat16* __restrict__ Alo,
    int lda, size_t astride,
    const __nv_bfloat16* __restrict__ Bhi, const __nv_bfloat16* __restrict__ Blo,
    int ldb, size_t bstride,
    int nchunks,
    const float* __restrict__ e0, const float* __restrict__ e1,
    float* __restrict__ out0) {
    extern __shared__ __align__(128) char dsm[];
    uint32_t sbase = smem_to_u32(dsm);
    int tid = threadIdx.x;
    int wid = tid >> 5, lane = tid & 31;
    int wm = wid >> 2, wn = wid & 3;          // warp grid 2(m) x 4(n)
    int b = blockIdx.z, m0 = blockIdx.y * 128, n0 = blockIdx.x * 128;

    const __nv_bfloat16* A_h = Ahi + (size_t)b * astride + (size_t)m0 * lda;
    const __nv_bfloat16* A_l = Alo + (size_t)b * astride + (size_t)m0 * lda;
    const __nv_bfloat16* B_h = Bhi + (size_t)b * bstride + (size_t)n0 * ldb;
    const __nv_bfloat16* B_l = Blo + (size_t)b * bstride + (size_t)n0 * ldb;

    uint32_t a_off[4], b_off[4];
    {
        int arow = lane & 15;
        uint32_t ahalf = (lane & 16) ? 16u : 0u;
        #pragma unroll
        for (int i = 0; i < 4; ++i)
            a_off[i] = (uint32_t)((wm * 64 + i * 16 + arow) * PITCH) + ahalf;
        int l16 = lane & 15;
        int brow = l16 & 7;
        uint32_t bhalf = (l16 & 8) ? 16u : 0u;
        #pragma unroll
        for (int j = 0; j < 4; ++j)
            b_off[j] = (uint32_t)((wn * 32 + j * 8 + brow) * PITCH) + bhalf;
    }

    float acc[4][4][4] = {};

    load_chunk(sbase, A_h, A_l, B_h, B_l, lda, ldb, 0, tid);
    CP_COMMIT();

    for (int j = 0; j < nchunks; ++j) {
        if (j + 1 < nchunks) {
            load_chunk(sbase + (uint32_t)((j + 1) & 1) * STAGE_B,
                       A_h, A_l, B_h, B_l, lda, ldb, (j + 1) * 32, tid);
            CP_COMMIT();
            CP_WAIT(1);
        } else {
            CP_WAIT(0);
        }
        __syncthreads();
        uint32_t st = sbase + (uint32_t)(j & 1) * STAGE_B;
        #pragma unroll
        for (int ks = 0; ks < 2; ++ks) {
            uint32_t koff = (uint32_t)(ks * 32);
            uint32_t ah[4][4], al[4][4], bh[4][2], bl[4][2];
            #pragma unroll
            for (int i = 0; i < 4; ++i) {
                LDSM_X4(ah[i], st + OFF_AH + a_off[i] + koff);
                LDSM_X4(al[i], st + OFF_AL + a_off[i] + koff);
            }
            #pragma unroll
            for (int jj = 0; jj < 4; ++jj) {
                LDSM_X2(bh[jj], st + OFF_BH + b_off[jj] + koff);
                LDSM_X2(bl[jj], st + OFF_BL + b_off[jj] + koff);
            }
            #pragma unroll
            for (int i = 0; i < 4; ++i)
                #pragma unroll
                for (int jj = 0; jj < 4; ++jj)
                    MMA_BF16(acc[i][jj], ah[i], bh[jj]);
            #pragma unroll
            for (int i = 0; i < 4; ++i)
                #pragma unroll
                for (int jj = 0; jj < 4; ++jj)
                    MMA_BF16(acc[i][jj], ah[i], bl[jj]);
            #pragma unroll
            for (int i = 0; i < 4; ++i)
                #pragma unroll
                for (int jj = 0; jj < 4; ++jj)
                    MMA_BF16(acc[i][jj], al[i], bh[jj]);
        }
        __syncthreads();   // close WAR: next iter's cp.async writes other buffer
    }

    // Epilogue: frag (i,jj): c0 (r, col), c1 (r, col+1), c2 (r+8, col), c3 (r+8, col+1)
    int gid = lane >> 2, tig = lane & 3;
    #pragma unroll
    for (int i = 0; i < 4; ++i) {
        int r0 = m0 + wm * 64 + i * 16 + gid;
        #pragma unroll
        for (int jj = 0; jj < 4; ++jj) {
            int col = n0 + wn * 32 + jj * 8 + tig * 2;
            float v0 = acc[i][jj][0], v1 = acc[i][jj][1];
            float v2 = acc[i][jj][2], v3 = acc[i][jj][3];
            if (EPI == 1) {
                float b0 = e0[col], b1v = e0[col + 1];
                float* d0 = g_hT + ((size_t)b * Tq + r0) * Cq + col;
                float* d1 = g_hT + ((size_t)b * Tq + r0 + 8) * Cq + col;
                *(float2*)d0 = float2{mishf(v0 + b0), mishf(v1 + b1v)};
                *(float2*)d1 = float2{mishf(v2 + b0), mishf(v3 + b1v)};
            } else if (EPI == 2) {
                float s0 = g_inv_pnorm[b * Cq + col], s1 = g_inv_pnorm[b * Cq + col + 1];
                float p0 = e0[b * Cq + col], p1 = e0[b * Cq + col + 1];
                float u0 = mishf(fmaf(v0, s0, p0)), u1 = mishf(fmaf(v1, s1, p1));
                float u2 = mishf(fmaf(v2, s0, p0)), u3 = mishf(fmaf(v3, s1, p1));
                __nv_bfloat16 h0, h1, h2, h3, l0, l1, l2, l3;
                bsplit(u0, h0, l0); bsplit(u1, h1, l1);
                bsplit(u2, h2, l2); bsplit(u3, h3, l3);
                size_t o0i = ((size_t)b * Tq + r0) * Cq + col;
                size_t o1i = ((size_t)b * Tq + r0 + 8) * Cq + col;
                *(__nv_bfloat162*)(g_tmphi + o0i) = __nv_bfloat162{h0, h1};
                *(__nv_bfloat162*)(g_tmphi + o1i) = __nv_bfloat162{h2, h3};
                *(__nv_bfloat162*)(g_tmplo + o0i) = __nv_bfloat162{l0, l1};
                *(__nv_bfloat162*)(g_tmplo + o1i) = __nv_bfloat162{l2, l3};
            } else {
                float b0 = e0[col], b1v = e0[col + 1];
                size_t o0i = ((size_t)b * Tq + r0) * Dq + col;
                size_t o1i = ((size_t)b * Tq + r0 + 8) * Dq + col;
                float2 x0 = *(const float2*)(e1 + o0i);
                float2 x1 = *(const float2*)(e1 + o1i);
                *(float2*)(out0 + o0i) = float2{v0 + b0 + x0.x, v1 + b1v + x0.y};
                *(float2*)(out0 + o1i) = float2{v2 + b0 + x1.x, v3 + b1v + x1.y};
            }
        }
    }
}

// ===========================================================================
extern "C" void kernel_launch(void* const* d_in, const int* in_sizes, int n_in,
                              void* d_out, int out_size) {
    const float* x   = (const float*)d_in[0];
    const float* d_w = (const float*)d_in[1];
    const float* d_g = (const float*)d_in[2];
    const float* d_b = (const float*)d_in[3];
    const float* p_w = (const float*)d_in[4];
    const float* p_g = (const float*)d_in[5];
    const float* p_b = (const float*)d_in[6];
    const float* w1  = (const float*)d_in[7];
    const float* b1  = (const float*)d_in[8];
    const float* w2  = (const float*)d_in[9];
    const float* b2  = (const float*)d_in[10];
    float* out = (float*)d_out;

    cudaFuncSetAttribute(mma_gemm<1>, cudaFuncAttributeMaxDynamicSharedMemorySize, SMEM_ALLOC);
    cudaFuncSetAttribute(mma_gemm<2>, cudaFuncAttributeMaxDynamicSharedMemorySize, SMEM_ALLOC);
    cudaFuncSetAttribute(mma_gemm<3>, cudaFuncAttributeMaxDynamicSharedMemorySize, SMEM_ALLOC);

    __nv_bfloat16 *xhi, *xlo, *w1hi, *w1lo, *w2hi, *w2lo;
    __nv_bfloat16 *convhi, *convlo, *pwhi, *pwlo, *tmphi, *tmplo;
    cudaGetSymbolAddress((void**)&xhi, g_xhi);
    cudaGetSymbolAddress((void**)&xlo, g_xlo);
    cudaGetSymbolAddress((void**)&w1hi, g_w1hi);
    cudaGetSymbolAddress((void**)&w1lo, g_w1lo);
    cudaGetSymbolAddress((void**)&w2hi, g_w2hi);
    cudaGetSymbolAddress((void**)&w2lo, g_w2lo);
    cudaGetSymbolAddress((void**)&convhi, g_convhi);
    cudaGetSymbolAddress((void**)&convlo, g_convlo);
    cudaGetSymbolAddress((void**)&pwhi, g_pwhi);
    cudaGetSymbolAddress((void**)&pwlo, g_pwlo);
    cudaGetSymbolAddress((void**)&tmphi, g_tmphi);
    cudaGetSymbolAddress((void**)&tmplo, g_tmplo);

    // Launch order: gemm1 at index 3 so ncu profiles it.
    split_kernel<<<(Bq * Tq * Dq / 4 + 255) / 256, 256>>>(x, xhi, xlo, Bq * Tq * Dq / 4);
    split_kernel<<<(Cq * Dq / 4 + 255) / 256, 256>>>(w1, w1hi, w1lo, Cq * Dq / 4);
    split_kernel<<<(Dq * Cq / 4 + 255) / 256, 256>>>(w2, w2hi, w2lo, Dq * Cq / 4);

    // GEMM1: h[b,t,c] = mish(x @ w1^T + b1)
    mma_gemm<1><<<dim3(Cq / 128, Tq / 128, Bq), 256, SMEM_ALLOC>>>(
        xhi, xlo, Dq, (size_t)Tq * Dq,
        w1hi, w1lo, Dq, 0,
        Dq / 32, b1, nullptr, nullptr);

    dnorm_kernel<<<Bq * Kq, 256>>>(d_w);
    pnorm_kernel<<<dim3(Bq, Cq / 256), 256>>>(p_w);
    pw_prep_kernel<<<dim3(Cq / 32, Cq / 32, Bq), 256>>>(p_w, p_g);

    // depthwise conv (on [t][c]) -> bf16 split
    conv_t_kernel<<<dim3(Cq / 512, Tq / 8, Bq), 256>>>(d_w, d_g, d_b);

    // GEMM2: tmp[b,t,o] = mish(inv_pnorm*(conv @ pw^T) + p_b)
    mma_gemm<2><<<dim3(Cq / 128, Tq / 128, Bq), 256, SMEM_ALLOC>>>(
        convhi, convlo, Cq, (size_t)Tq * Cq,
        pwhi, pwlo, Cq, (size_t)Cq * Cq,
        Cq / 32, p_b, nullptr, nullptr);

    // GEMM3: out[b,t,d] = tmp @ w2^T + b2 + x
    mma_gemm<3><<<dim3(Dq / 128, Tq / 128, Bq), 256, SMEM_ALLOC>>>(
        tmphi, tmplo, Cq, (size_t)Tq * Cq,
        w2hi, w2lo, Cq, 0,
        Cq / 32, b2, x, out);
}

// round 7
// speedup vs baseline: 2.3378x; 1.1801x over previous
#include <cuda_runtime.h>
#include <cuda_bf16.h>
#include <cstdint>
#include <math.h>

#define Bq  16
#define Tq  1024
#define Dq  256
#define Cq  1024
#define Kq  9

// ===========================================================================
// Helpers (baseline PTX only — no 'a'-suffix features)
// ===========================================================================
__device__ __forceinline__ uint32_t smem_to_u32(const void* p) {
    uint32_t a;
    asm("{ .reg .u64 t; cvta.to.shared.u64 t, %1; cvt.u32.u64 %0, t; }" : "=r"(a) : "l"(p));
    return a;
}
#define LDSM_X4(r, a) \
    asm volatile("ldmatrix.sync.aligned.m8n8.x4.shared.b16 {%0,%1,%2,%3}, [%4];" \
        : "=r"((r)[0]), "=r"((r)[1]), "=r"((r)[2]), "=r"((r)[3]) : "r"(a))
#define LDSM_X2(r, a) \
    asm volatile("ldmatrix.sync.aligned.m8n8.x2.shared.b16 {%0,%1}, [%2];" \
        : "=r"((r)[0]), "=r"((r)[1]) : "r"(a))
#define MMA_BF16(d, a, bb) \
    asm volatile("mma.sync.aligned.m16n8k16.row.col.f32.bf16.bf16.f32 " \
        "{%0,%1,%2,%3}, {%4,%5,%6,%7}, {%8,%9}, {%0,%1,%2,%3};" \
        : "+f"((d)[0]), "+f"((d)[1]), "+f"((d)[2]), "+f"((d)[3]) \
        : "r"((a)[0]), "r"((a)[1]), "r"((a)[2]), "r"((a)[3]), \
          "r"((bb)[0]), "r"((bb)[1]))

#define MBARRIER_INIT(mb, c) \
    asm volatile("mbarrier.init.shared.b64 [%0], %1;" :: "r"((uint32_t)(mb)), "r"((uint32_t)(c)) : "memory")
#define MBARRIER_WAIT_PARITY(mb, ph) do { \
    uint32_t _m = (uint32_t)(mb); uint32_t _p = (uint32_t)(ph); uint32_t _d; \
    asm volatile("{\n\t.reg .pred p;\n\t" \
        "mbarrier.try_wait.parity.acquire.cta.shared::cta.b64 p, [%1], %2;\n\t" \
        "selp.b32 %0, 1, 0, p;\n\t}" : "=r"(_d) : "r"(_m), "r"(_p) : "memory"); \
    if (!_d) { \
        asm volatile("{\n\t.reg .pred P1;\n\t" \
            "WL_%=:\n\t" \
            "mbarrier.try_wait.parity.acquire.cta.shared::cta.b64 P1, [%0], %1, 0x989680;\n\t" \
            "@P1 bra.uni WD_%=;\n\t" \
            "bra.uni WL_%=;\n\t" \
            "WD_%=:\n\t}" :: "r"(_m), "r"(_p) : "memory"); \
    } } while (0)

__device__ __forceinline__ void bulk_ld(uint32_t dst, const void* src, uint32_t mb) {
    asm volatile(
        "cp.async.bulk.shared::cta.global.mbarrier::complete_tx::bytes [%0], [%1], %2, [%3];"
        :: "r"(dst), "l"(src), "r"(8192u), "r"(mb) : "memory");
}
__device__ __forceinline__ void mbar_expect(uint32_t mb, uint32_t bytes) {
    asm volatile("mbarrier.arrive.expect_tx.shared.b64 _, [%0], %1;"
        :: "r"(mb), "r"(bytes) : "memory");
}

// mish(x) = x * w / (w + 2),  w = e^x (e^x + 2)
__device__ __forceinline__ float mishf(float x) {
    if (x > 15.f) return x;
    float t = __expf(x);
    float w = t * (t + 2.f);
    return x * __fdividef(w, w + 2.f);
}
__device__ __forceinline__ void bsplit(float v, __nv_bfloat16& h, __nv_bfloat16& l) {
    h = __float2bfloat16(v);
    l = __float2bfloat16(v - __bfloat162float(h));
}
__device__ __forceinline__ uint32_t pkbf(__nv_bfloat16 a, __nv_bfloat16 b) {
    __nv_bfloat162 t{a, b};
    return *(uint32_t*)&t;
}

// Packed layout: matrix [R rows][K cols] bf16 -> blocks of 128 rows x 32 k
// (8192 B, chunk-contiguous). Within block: phys row p = r>>1 (128 B),
// 16B segment index = (((r&1)<<2)|s) ^ (p&7), s = (k%32)>>3.
// Block order: [m][q] with q fastest (nq = K/32 chunks per row-block).
__device__ __forceinline__ size_t pk_off(int m, int q, int r, int s, int nq) {
    int p = r >> 1;
    int seg = ((((r & 1) << 2) | s) ^ (p & 7));
    return ((size_t)(m * nq + q) << 13) + ((size_t)p << 7) + ((size_t)seg << 4);
}

// ===========================================================================
// Device scratch
// ===========================================================================
__device__ __align__(16) __nv_bfloat16 g_xhi[(size_t)Bq * Tq * Dq];     // packed
__device__ __align__(16) __nv_bfloat16 g_xlo[(size_t)Bq * Tq * Dq];
__device__ __align__(16) __nv_bfloat16 g_w1hi[(size_t)Cq * Dq];         // packed
__device__ __align__(16) __nv_bfloat16 g_w1lo[(size_t)Cq * Dq];
__device__ __align__(16) __nv_bfloat16 g_w2hi[(size_t)Dq * Cq];         // packed
__device__ __align__(16) __nv_bfloat16 g_w2lo[(size_t)Dq * Cq];
__device__ __align__(16) float g_hT[(size_t)Bq * Tq * Cq];              // plain [b][t][c]
__device__ __align__(16) __nv_bfloat16 g_convhi[(size_t)Bq * Tq * Cq];  // packed
__device__ __align__(16) __nv_bfloat16 g_convlo[(size_t)Bq * Tq * Cq];
__device__ __align__(16) __nv_bfloat16 g_pwhi[(size_t)Bq * Cq * Cq];    // packed
__device__ __align__(16) __nv_bfloat16 g_pwlo[(size_t)Bq * Cq * Cq];
__device__ __align__(16) __nv_bfloat16 g_tmphi[(size_t)Bq * Tq * Cq];   // packed
__device__ __align__(16) __nv_bfloat16 g_tmplo[(size_t)Bq * Tq * Cq];
__device__ float g_inv_pnorm[Bq * Cq];
__device__ float g_inv_dnorm[Bq * Kq];

// ===========================================================================
// Prep kernels
// ===========================================================================
// Split fp32 [R][K] into packed bf16 hi/lo. One thread per 16B output segment.
__global__ void split_pack_kernel(const float* __restrict__ src,
                                  __nv_bfloat16* __restrict__ hi,
                                  __nv_bfloat16* __restrict__ lo,
                                  int lgspr, int nq, int total) {
    int idx = blockIdx.x * 256 + threadIdx.x;
    if (idx >= total) return;
    int spr = 1 << lgspr;            // segments per row = K/8
    int r_all = idx >> lgspr;
    int kseg = idx & (spr - 1);
    int q = kseg >> 2, s = kseg & 3;
    int m = r_all >> 7, r = r_all & 127;
    const float* sp = src + ((size_t)r_all << (lgspr + 3)) + ((size_t)kseg << 3);
    float4 v0 = *(const float4*)sp;
    float4 v1 = *(const float4*)(sp + 4);
    __nv_bfloat16 h[8], l[8];
    bsplit(v0.x, h[0], l[0]); bsplit(v0.y, h[1], l[1]);
    bsplit(v0.z, h[2], l[2]); bsplit(v0.w, h[3], l[3]);
    bsplit(v1.x, h[4], l[4]); bsplit(v1.y, h[5], l[5]);
    bsplit(v1.z, h[6], l[6]); bsplit(v1.w, h[7], l[7]);
    size_t off = pk_off(m, q, r, s, nq);
    uint4 hv = make_uint4(pkbf(h[0],h[1]), pkbf(h[2],h[3]), pkbf(h[4],h[5]), pkbf(h[6],h[7]));
    uint4 lv = make_uint4(pkbf(l[0],l[1]), pkbf(l[2],l[3]), pkbf(l[4],l[5]), pkbf(l[6],l[7]));
    *(uint4*)((char*)hi + off) = hv;
    *(uint4*)((char*)lo + off) = lv;
}

__global__ void dnorm_kernel(const float* __restrict__ d_w) {
    int bk = blockIdx.x;
    int b = bk / Kq, k = bk % Kq;
    float s = 0.f;
    for (int c = threadIdx.x; c < Cq; c += 256) {
        float v = d_w[((size_t)b * Cq + c) * Kq + k];
        s = fmaf(v, v, s);
    }
    __shared__ float red[256];
    red[threadIdx.x] = s;
    __syncthreads();
    for (int off = 128; off > 0; off >>= 1) {
        if (threadIdx.x < off) red[threadIdx.x] += red[threadIdx.x + off];
        __syncthreads();
    }
    if (threadIdx.x == 0)
        g_inv_dnorm[bk] = 1.f / fmaxf(sqrtf(red[0]), 1e-12f);
}

__global__ void pnorm_kernel(const float* __restrict__ p_w) {
    int b = blockIdx.x;
    int o = blockIdx.y * 256 + threadIdx.x;
    const float* base = p_w + (size_t)b * Cq * Cq + o;
    float s = 0.f;
    #pragma unroll 4
    for (int c = 0; c < Cq; ++c) {
        float v = base[(size_t)c * Cq];
        s = fmaf(v, v, s);
    }
    g_inv_pnorm[b * Cq + o] = 1.f / fmaxf(sqrtf(s), 1e-12f);
}

// Transpose p_w[b][c][o]*p_g[b][c] -> packed [b*1024+o rows][c cols] bf16 split
__global__ __launch_bounds__(256) void pw_prep_kernel(
    const float* __restrict__ p_w, const float* __restrict__ p_g) {
    int b = blockIdx.z;
    int c0 = blockIdx.x * 32;
    int o0 = blockIdx.y * 32;
    __shared__ float s[32][33];
    __shared__ float pgs[32];
    int tid = threadIdx.x;
    int x = tid & 31, y = tid >> 5;
    if (tid < 32) pgs[tid] = p_g[b * Cq + c0 + tid];
    const float* in = p_w + (size_t)b * Cq * Cq;
    #pragma unroll
    for (int yy = 0; yy < 4; ++yy) {
        int c = c0 + y * 4 + yy;
        s[y * 4 + yy][x] = in[(size_t)c * Cq + o0 + x];
    }
    __syncthreads();
    int q = c0 >> 5;
    int sseg = x >> 3;
    int ins = (x & 7) << 1;
    #pragma unroll
    for (int yy = 0; yy < 4; ++yy) {
        int o = o0 + y * 4 + yy;
        float w = s[x][y * 4 + yy] * pgs[x];
        __nv_bfloat16 h, l;
        bsplit(w, h, l);
        int m = (b << 3) | (o >> 7);
        size_t off = pk_off(m, q, o & 127, sseg, 32) + ins;
        *(__nv_bfloat16*)((char*)g_pwhi + off) = h;
        *(__nv_bfloat16*)((char*)g_pwlo + off) = l;
    }
}

// ===========================================================================
// Depthwise conv on [t][c] layout -> packed bf16 split
// ===========================================================================
__global__ __launch_bounds__(256) void conv_t_kernel(
    const float* __restrict__ d_w, const float* __restrict__ d_g,
    const float* __restrict__ d_b) {
    int b  = blockIdx.z;
    int t0 = blockIdx.y * 8;
    int ch = blockIdx.x * 512;
    __shared__ float s[16][512];
    const float* h = g_hT + (size_t)b * Tq * Cq;
    int tid = threadIdx.x;
    #pragma unroll
    for (int i = 0; i < 8; ++i) {
        int idx = tid + i * 256;
        int r  = idx >> 7;
        int cc = (idx & 127) * 4;
        int t = t0 - 4 + r;
        float4 v = (t >= 0 && t < Tq)
            ? *(const float4*)(h + (size_t)t * Cq + ch + cc)
            : make_float4(0.f, 0.f, 0.f, 0.f);
        *(float4*)&s[r][cc] = v;
    }
    __syncthreads();
    int cg = (tid & 127) * 4;
    int tsub = tid >> 7;
    int c = ch + cg;
    float w[Kq][4], bias[4];
    #pragma unroll
    for (int qd = 0; qd < 4; ++qd) {
        float g = d_g[b * Cq + c + qd];
        bias[qd] = d_b[b * Cq + c + qd];
        #pragma unroll
        for (int k = 0; k < Kq; ++k)
            w[k][qd] = d_w[((size_t)b * Cq + c + qd) * Kq + k] * g_inv_dnorm[b * Kq + k] * g;
    }
    int qc = c >> 5;
    int sc = (c >> 3) & 3;
    int ins = (c & 7) << 1;      // 0 or 8
    #pragma unroll
    for (int i = 0; i < 4; ++i) {
        int tl = tsub * 4 + i;
        int t = t0 + tl;
        float4 acc = make_float4(bias[0], bias[1], bias[2], bias[3]);
        #pragma unroll
        for (int k = 0; k < Kq; ++k) {
            float4 vv = *(float4*)&s[tl + k][cg];
            acc.x = fmaf(vv.x, w[k][0], acc.x);
            acc.y = fmaf(vv.y, w[k][1], acc.y);
            acc.z = fmaf(vv.z, w[k][2], acc.z);
            acc.w = fmaf(vv.w, w[k][3], acc.w);
        }
        __nv_bfloat16 h0, h1, h2, h3, l0, l1, l2, l3;
        bsplit(acc.x, h0, l0); bsplit(acc.y, h1, l1);
        bsplit(acc.z, h2, l2); bsplit(acc.w, h3, l3);
        int m = (b << 3) | (t >> 7);
        size_t off = pk_off(m, qc, t & 127, sc, 32) + ins;
        *(uint2*)((char*)g_convhi + off) = make_uint2(pkbf(h0,h1), pkbf(h2,h3));
        *(uint2*)((char*)g_convlo + off) = make_uint2(pkbf(l0,l1), pkbf(l2,l3));
    }
}

// ===========================================================================
// mma.sync bf16-split GEMM with cp.async.bulk chunk loads.
// CTA tile 128x128, K-chunk 32, 2 stages x 32KB, 2 CTAs/SM.
// Stage layout: [AH 8K][AL 8K][BH 8K][BL 8K]
// ===========================================================================
#define STAGE_B 32768
#define SMEM_ALLOC (1024 + 128 + 2 * STAGE_B)

__device__ __forceinline__ void issue_chunk(uint32_t st0, uint32_t mb0, uint32_t mb1,
    const char* Ah, const char* Al, const char* Bh, const char* Bl, int q) {
    uint32_t mb = (q & 1) ? mb1 : mb0;
    uint32_t dst = st0 + (uint32_t)(q & 1) * STAGE_B;
    size_t qo = (size_t)q << 13;
    mbar_expect(mb, 32768u);
    bulk_ld(dst,          Ah + qo, mb);
    bulk_ld(dst + 8192u,  Al + qo, mb);
    bulk_ld(dst + 16384u, Bh + qo, mb);
    bulk_ld(dst + 24576u, Bl + qo, mb);
}

template <int EPI>
__global__ __launch_bounds__(256, 2) void mma_gemm(
    const __nv_bfloat16* __restrict__ Ahi, const __nv_bfloat16* __restrict__ Alo,
    int a_mpb,
    const __nv_bfloat16* __restrict__ Bhi, const __nv_bfloat16* __restrict__ Blo,
    int b_mpb,
    int nchunks,
    const float* __restrict__ e0, const float* __restrict__ e1,
    float* __restrict__ out0) {
    extern __shared__ __align__(128) char dsm[];
    uint32_t raw = smem_to_u32(dsm);
    uint32_t hdr = (raw + 1023u) & ~1023u;
    uint32_t mb0 = hdr, mb1 = hdr + 8;
    uint32_t st0 = hdr + 128;
    int tid = threadIdx.x;
    int wid = tid >> 5, lane = tid & 31;
    int wm = wid >> 2, wn = wid & 3;          // warp grid 2(m) x 4(n)
    int b = blockIdx.z, m0 = blockIdx.y * 128, n0 = blockIdx.x * 128;

    const char* Abh = (const char*)Ahi + ((size_t)((b * a_mpb + blockIdx.y) * nchunks) << 13);
    const char* Abl = (const char*)Alo + ((size_t)((b * a_mpb + blockIdx.y) * nchunks) << 13);
    const char* Bbh = (const char*)Bhi + ((size_t)((b * b_mpb + blockIdx.x) * nchunks) << 13);
    const char* Bbl = (const char*)Blo + ((size_t)((b * b_mpb + blockIdx.x) * nchunks) << 13);

    if (tid == 0) { MBARRIER_INIT(mb0, 1); MBARRIER_INIT(mb1, 1); }
    __syncthreads();
    if (tid == 0) {
        issue_chunk(st0, mb0, mb1, Abh, Abl, Bbh, Bbl, 0);
        issue_chunk(st0, mb0, mb1, Abh, Abl, Bbh, Bbl, 1);
    }

    // ldmatrix tile-relative swizzled offsets: aoff[i][ks], boff[j][ks]
    uint32_t aoff[4][2], boff[4][2];
    {
        int rla = lane & 15, sha = (lane >> 4) & 1;
        #pragma unroll
        for (int i = 0; i < 4; ++i) {
            int r = wm * 64 + i * 16 + rla;
            int p = r >> 1, x4 = (r & 1) << 2, mk = p & 7, rb = p << 7;
            aoff[i][0] = rb + (((x4 | sha) ^ mk) << 4);
            aoff[i][1] = rb + (((x4 | (2 + sha)) ^ mk) << 4);
        }
        int rlb = lane & 7, shb = (lane >> 3) & 1;
        #pragma unroll
        for (int j = 0; j < 4; ++j) {
            int r = wn * 32 + j * 8 + rlb;
            int p = r >> 1, x4 = (r & 1) << 2, mk = p & 7, rb = p << 7;
            boff[j][0] = rb + (((x4 | shb) ^ mk) << 4);
            boff[j][1] = rb + (((x4 | (2 + shb)) ^ mk) << 4);
        }
    }

    float acc[4][4][4] = {};

    for (int q = 0; q < nchunks; ++q) {
        MBARRIER_WAIT_PARITY((q & 1) ? mb1 : mb0, (q >> 1) & 1);
        uint32_t st = st0 + (uint32_t)(q & 1) * STAGE_B;
        #pragma unroll
        for (int ks = 0; ks < 2; ++ks) {
            uint32_t ah[4][4], al[4][4], bh[4][2], bl[4][2];
            #pragma unroll
            for (int i = 0; i < 4; ++i) {
                LDSM_X4(ah[i], st + aoff[i][ks]);
                LDSM_X4(al[i], st + 8192u + aoff[i][ks]);
            }
            #pragma unroll
            for (int jj = 0; jj < 4; ++jj) {
                LDSM_X2(bh[jj], st + 16384u + boff[jj][ks]);
                LDSM_X2(bl[jj], st + 24576u + boff[jj][ks]);
            }
            #pragma unroll
            for (int i = 0; i < 4; ++i)
                #pragma unroll
                for (int jj = 0; jj < 4; ++jj)
                    MMA_BF16(acc[i][jj], ah[i], bh[jj]);
            #pragma unroll
            for (int i = 0; i < 4; ++i)
                #pragma unroll
                for (int jj = 0; jj < 4; ++jj)
                    MMA_BF16(acc[i][jj], ah[i], bl[jj]);
            #pragma unroll
            for (int i = 0; i < 4; ++i)
                #pragma unroll
                for (int jj = 0; jj < 4; ++jj)
                    MMA_BF16(acc[i][jj], al[i], bh[jj]);
        }
        __syncthreads();   // all warps done reading buf(q&1) before its reuse
        if (q + 2 < nchunks && tid == 0)
            issue_chunk(st0, mb0, mb1, Abh, Abl, Bbh, Bbl, q + 2);
    }

    // Epilogue: frag (i,jj): c0 (r, col), c1 (r, col+1), c2 (r+8, col), c3 (r+8, col+1)
    int gid = lane >> 2, tig = lane & 3;
    #pragma unroll
    for (int i = 0; i < 4; ++i) {
        int r0 = m0 + wm * 64 + i * 16 + gid;
        #pragma unroll
        for (int jj = 0; jj < 4; ++jj) {
            int col = n0 + wn * 32 + jj * 8 + tig * 2;
            float v0 = acc[i][jj][0], v1 = acc[i][jj][1];
            float v2 = acc[i][jj][2], v3 = acc[i][jj][3];
            if (EPI == 1) {
                float b0 = e0[col], b1v = e0[col + 1];
                float* d0 = g_hT + ((size_t)b * Tq + r0) * Cq + col;
                float* d1 = g_hT + ((size_t)b * Tq + r0 + 8) * Cq + col;
                *(float2*)d0 = float2{mishf(v0 + b0), mishf(v1 + b1v)};
                *(float2*)d1 = float2{mishf(v2 + b0), mishf(v3 + b1v)};
            } else if (EPI == 2) {
                float s0 = g_inv_pnorm[b * Cq + col], s1 = g_inv_pnorm[b * Cq + col + 1];
                float p0 = e0[b * Cq + col], p1 = e0[b * Cq + col + 1];
                float u0 = mishf(fmaf(v0, s0, p0)), u1 = mishf(fmaf(v1, s1, p1));
                float u2 = mishf(fmaf(v2, s0, p0)), u3 = mishf(fmaf(v3, s1, p1));
                __nv_bfloat16 h0, h1, h2, h3, l0, l1, l2, l3;
                bsplit(u0, h0, l0); bsplit(u1, h1, l1);
                bsplit(u2, h2, l2); bsplit(u3, h3, l3);
                int m = (b << 3) | (r0 >> 7);
                int qp = col >> 5, sp = (col >> 3) & 3, ins = (col & 7) << 1;
                size_t oA = pk_off(m, qp, r0 & 127, sp, 32) + ins;
                size_t oB = pk_off(m, qp, (r0 + 8) & 127, sp, 32) + ins;
                *(uint32_t*)((char*)g_tmphi + oA) = pkbf(h0, h1);
                *(uint32_t*)((char*)g_tmphi + oB) = pkbf(h2, h3);
                *(uint32_t*)((char*)g_tmplo + oA) = pkbf(l0, l1);
                *(uint32_t*)((char*)g_tmplo + oB) = pkbf(l2, l3);
            } else {
                float b0 = e0[col], b1v = e0[col + 1];
                size_t o0i = ((size_t)b * Tq + r0) * Dq + col;
                size_t o1i = ((size_t)b * Tq + r0 + 8) * Dq + col;
                float2 x0 = *(const float2*)(e1 + o0i);
                float2 x1 = *(const float2*)(e1 + o1i);
                *(float2*)(out0 + o0i) = float2{v0 + b0 + x0.x, v1 + b1v + x0.y};
                *(float2*)(out0 + o1i) = float2{v2 + b0 + x1.x, v3 + b1v + x1.y};
            }
        }
    }
}

// ===========================================================================
extern "C" void kernel_launch(void* const* d_in, const int* in_sizes, int n_in,
                              void* d_out, int out_size) {
    const float* x   = (const float*)d_in[0];
    const float* d_w = (const float*)d_in[1];
    const float* d_g = (const float*)d_in[2];
    const float* d_b = (const float*)d_in[3];
    const float* p_w = (const float*)d_in[4];
    const float* p_g = (const float*)d_in[5];
    const float* p_b = (const float*)d_in[6];
    const float* w1  = (const float*)d_in[7];
    const float* b1  = (const float*)d_in[8];
    const float* w2  = (const float*)d_in[9];
    const float* b2  = (const float*)d_in[10];
    float* out = (float*)d_out;

    cudaFuncSetAttribute(mma_gemm<1>, cudaFuncAttributeMaxDynamicSharedMemorySize, SMEM_ALLOC);
    cudaFuncSetAttribute(mma_gemm<2>, cudaFuncAttributeMaxDynamicSharedMemorySize, SMEM_ALLOC);
    cudaFuncSetAttribute(mma_gemm<3>, cudaFuncAttributeMaxDynamicSharedMemorySize, SMEM_ALLOC);

    __nv_bfloat16 *xhi, *xlo, *w1hi, *w1lo, *w2hi, *w2lo;
    __nv_bfloat16 *convhi, *convlo, *pwhi, *pwlo, *tmphi, *tmplo;
    cudaGetSymbolAddress((void**)&xhi, g_xhi);
    cudaGetSymbolAddress((void**)&xlo, g_xlo);
    cudaGetSymbolAddress((void**)&w1hi, g_w1hi);
    cudaGetSymbolAddress((void**)&w1lo, g_w1lo);
    cudaGetSymbolAddress((void**)&w2hi, g_w2hi);
    cudaGetSymbolAddress((void**)&w2lo, g_w2lo);
    cudaGetSymbolAddress((void**)&convhi, g_convhi);
    cudaGetSymbolAddress((void**)&convlo, g_convlo);
    cudaGetSymbolAddress((void**)&pwhi, g_pwhi);
    cudaGetSymbolAddress((void**)&pwlo, g_pwlo);
    cudaGetSymbolAddress((void**)&tmphi, g_tmphi);
    cudaGetSymbolAddress((void**)&tmplo, g_tmplo);

    // Packing: x (R=16384,K=256,nq=8,lgspr=5), w1 (R=1024,K=256), w2 (R=256,K=1024,nq=32,lgspr=7)
    split_pack_kernel<<<(Bq * Tq * Dq / 8 + 255) / 256, 256>>>(x, xhi, xlo, 5, 8, Bq * Tq * Dq / 8);
    split_pack_kernel<<<(Cq * Dq / 8 + 255) / 256, 256>>>(w1, w1hi, w1lo, 5, 8, Cq * Dq / 8);
    split_pack_kernel<<<(Dq * Cq / 8 + 255) / 256, 256>>>(w2, w2hi, w2lo, 7, 32, Dq * Cq / 8);

    // GEMM1 at launch index 3 (ncu profiles it): h = mish(x @ w1^T + b1)
    mma_gemm<1><<<dim3(Cq / 128, Tq / 128, Bq), 256, SMEM_ALLOC>>>(
        xhi, xlo, Tq / 128, w1hi, w1lo, 0, Dq / 32, b1, nullptr, nullptr);

    dnorm_kernel<<<Bq * Kq, 256>>>(d_w);
    pnorm_kernel<<<dim3(Bq, Cq / 256), 256>>>(p_w);
    pw_prep_kernel<<<dim3(Cq / 32, Cq / 32, Bq), 256>>>(p_w, p_g);

    conv_t_kernel<<<dim3(Cq / 512, Tq / 8, Bq), 256>>>(d_w, d_g, d_b);

    // GEMM2: tmp = mish(inv_pnorm*(conv @ pw^T) + p_b)
    mma_gemm<2><<<dim3(Cq / 128, Tq / 128, Bq), 256, SMEM_ALLOC>>>(
        convhi, convlo, Tq / 128, pwhi, pwlo, Cq / 128, Cq / 32, p_b, nullptr, nullptr);

    // GEMM3: out = tmp @ w2^T + b2 + x
    mma_gemm<3><<<dim3(Dq / 128, Tq / 128, Bq), 256, SMEM_ALLOC>>>(
        tmphi, tmplo, Tq / 128, w2hi, w2lo, 0, Cq / 32, b2, x, out);
}

// round 8
// speedup vs baseline: 2.7979x; 1.1968x over previous
#include <cuda_runtime.h>
#include <cuda_bf16.h>
#include <cstdint>
#include <math.h>

#define Bq  16
#define Tq  1024
#define Dq  256
#define Cq  1024
#define Kq  9

// ===========================================================================
// Helpers (baseline PTX only — no 'a'-suffix features)
// ===========================================================================
__device__ __forceinline__ uint32_t smem_to_u32(const void* p) {
    uint32_t a;
    asm("{ .reg .u64 t; cvta.to.shared.u64 t, %1; cvt.u32.u64 %0, t; }" : "=r"(a) : "l"(p));
    return a;
}
#define LDSM_X4(r, a) \
    asm volatile("ldmatrix.sync.aligned.m8n8.x4.shared.b16 {%0,%1,%2,%3}, [%4];" \
        : "=r"((r)[0]), "=r"((r)[1]), "=r"((r)[2]), "=r"((r)[3]) : "r"(a))
#define MMA_BF16(d, a, bb) \
    asm volatile("mma.sync.aligned.m16n8k16.row.col.f32.bf16.bf16.f32 " \
        "{%0,%1,%2,%3}, {%4,%5,%6,%7}, {%8,%9}, {%0,%1,%2,%3};" \
        : "+f"((d)[0]), "+f"((d)[1]), "+f"((d)[2]), "+f"((d)[3]) \
        : "r"((a)[0]), "r"((a)[1]), "r"((a)[2]), "r"((a)[3]), \
          "r"((bb)[0]), "r"((bb)[1]))

#define MBARRIER_INIT(mb, c) \
    asm volatile("mbarrier.init.shared.b64 [%0], %1;" :: "r"((uint32_t)(mb)), "r"((uint32_t)(c)) : "memory")
#define MBARRIER_WAIT_PARITY(mb, ph) do { \
    uint32_t _m = (uint32_t)(mb); uint32_t _p = (uint32_t)(ph); uint32_t _d; \
    asm volatile("{\n\t.reg .pred p;\n\t" \
        "mbarrier.try_wait.parity.acquire.cta.shared::cta.b64 p, [%1], %2;\n\t" \
        "selp.b32 %0, 1, 0, p;\n\t}" : "=r"(_d) : "r"(_m), "r"(_p) : "memory"); \
    if (!_d) { \
        asm volatile("{\n\t.reg .pred P1;\n\t" \
            "WL_%=:\n\t" \
            "mbarrier.try_wait.parity.acquire.cta.shared::cta.b64 P1, [%0], %1, 0x989680;\n\t" \
            "@P1 bra.uni WD_%=;\n\t" \
            "bra.uni WL_%=;\n\t" \
            "WD_%=:\n\t}" :: "r"(_m), "r"(_p) : "memory"); \
    } } while (0)

__device__ __forceinline__ void bulk_ld(uint32_t dst, const void* src, uint32_t mb) {
    asm volatile(
        "cp.async.bulk.shared::cta.global.mbarrier::complete_tx::bytes [%0], [%1], %2, [%3];"
        :: "r"(dst), "l"(src), "r"(8192u), "r"(mb) : "memory");
}
__device__ __forceinline__ void mbar_expect(uint32_t mb, uint32_t bytes) {
    asm volatile("mbarrier.arrive.expect_tx.shared.b64 _, [%0], %1;"
        :: "r"(mb), "r"(bytes) : "memory");
}

// mish(x) = x * w / (w + 2),  w = e^x (e^x + 2)
__device__ __forceinline__ float mishf(float x) {
    if (x > 15.f) return x;
    float t = __expf(x);
    float w = t * (t + 2.f);
    return x * __fdividef(w, w + 2.f);
}
__device__ __forceinline__ void bsplit(float v, __nv_bfloat16& h, __nv_bfloat16& l) {
    h = __float2bfloat16(v);
    l = __float2bfloat16(v - __bfloat162float(h));
}
__device__ __forceinline__ uint32_t pkbf(__nv_bfloat16 a, __nv_bfloat16 b) {
    __nv_bfloat162 t{a, b};
    return *(uint32_t*)&t;
}

// Packed layout: matrix [R rows][K cols] bf16 -> blocks of 128 rows x 32 k
// (8192 B, chunk-contiguous). Within block: phys row p = r>>1 (128 B),
// 16B segment index = (((r&1)<<2)|s) ^ (p&7), s = (k%32)>>3.
// Block order: [m][q] with q fastest (nq = K/32 chunks per row-block).
__device__ __forceinline__ size_t pk_off(int m, int q, int r, int s, int nq) {
    int p = r >> 1;
    int seg = ((((r & 1) << 2) | s) ^ (p & 7));
    return ((size_t)(m * nq + q) << 13) + ((size_t)p << 7) + ((size_t)seg << 4);
}

// ===========================================================================
// Device scratch
// ===========================================================================
__device__ __align__(16) __nv_bfloat16 g_xhi[(size_t)Bq * Tq * Dq];     // packed
__device__ __align__(16) __nv_bfloat16 g_xlo[(size_t)Bq * Tq * Dq];
__device__ __align__(16) __nv_bfloat16 g_w1hi[(size_t)Cq * Dq];         // packed
__device__ __align__(16) __nv_bfloat16 g_w1lo[(size_t)Cq * Dq];
__device__ __align__(16) __nv_bfloat16 g_w2hi[(size_t)Dq * Cq];         // packed
__device__ __align__(16) __nv_bfloat16 g_w2lo[(size_t)Dq * Cq];
__device__ __align__(16) float g_hT[(size_t)Bq * Tq * Cq];              // plain [b][t][c]
__device__ __align__(16) __nv_bfloat16 g_convhi[(size_t)Bq * Tq * Cq];  // packed
__device__ __align__(16) __nv_bfloat16 g_convlo[(size_t)Bq * Tq * Cq];
__device__ __align__(16) __nv_bfloat16 g_pwhi[(size_t)Bq * Cq * Cq];    // packed
__device__ __align__(16) __nv_bfloat16 g_pwlo[(size_t)Bq * Cq * Cq];
__device__ __align__(16) __nv_bfloat16 g_tmphi[(size_t)Bq * Tq * Cq];   // packed
__device__ __align__(16) __nv_bfloat16 g_tmplo[(size_t)Bq * Tq * Cq];
__device__ float g_inv_pnorm[Bq * Cq];
__device__ float g_inv_dnorm[Bq * Kq];

// ===========================================================================
// Prep kernels
// ===========================================================================
__global__ void split_pack_kernel(const float* __restrict__ src,
                                  __nv_bfloat16* __restrict__ hi,
                                  __nv_bfloat16* __restrict__ lo,
                                  int lgspr, int nq, int total) {
    int idx = blockIdx.x * 256 + threadIdx.x;
    if (idx >= total) return;
    int spr = 1 << lgspr;            // segments per row = K/8
    int r_all = idx >> lgspr;
    int kseg = idx & (spr - 1);
    int q = kseg >> 2, s = kseg & 3;
    int m = r_all >> 7, r = r_all & 127;
    const float* sp = src + ((size_t)r_all << (lgspr + 3)) + ((size_t)kseg << 3);
    float4 v0 = *(const float4*)sp;
    float4 v1 = *(const float4*)(sp + 4);
    __nv_bfloat16 h[8], l[8];
    bsplit(v0.x, h[0], l[0]); bsplit(v0.y, h[1], l[1]);
    bsplit(v0.z, h[2], l[2]); bsplit(v0.w, h[3], l[3]);
    bsplit(v1.x, h[4], l[4]); bsplit(v1.y, h[5], l[5]);
    bsplit(v1.z, h[6], l[6]); bsplit(v1.w, h[7], l[7]);
    size_t off = pk_off(m, q, r, s, nq);
    uint4 hv = make_uint4(pkbf(h[0],h[1]), pkbf(h[2],h[3]), pkbf(h[4],h[5]), pkbf(h[6],h[7]));
    uint4 lv = make_uint4(pkbf(l[0],l[1]), pkbf(l[2],l[3]), pkbf(l[4],l[5]), pkbf(l[6],l[7]));
    *(uint4*)((char*)hi + off) = hv;
    *(uint4*)((char*)lo + off) = lv;
}

__global__ void dnorm_kernel(const float* __restrict__ d_w) {
    int bk = blockIdx.x;
    int b = bk / Kq, k = bk % Kq;
    float s = 0.f;
    for (int c = threadIdx.x; c < Cq; c += 256) {
        float v = d_w[((size_t)b * Cq + c) * Kq + k];
        s = fmaf(v, v, s);
    }
    __shared__ float red[256];
    red[threadIdx.x] = s;
    __syncthreads();
    for (int off = 128; off > 0; off >>= 1) {
        if (threadIdx.x < off) red[threadIdx.x] += red[threadIdx.x + off];
        __syncthreads();
    }
    if (threadIdx.x == 0)
        g_inv_dnorm[bk] = 1.f / fmaxf(sqrtf(red[0]), 1e-12f);
}

__global__ void pnorm_kernel(const float* __restrict__ p_w) {
    int b = blockIdx.x;
    int o = blockIdx.y * 256 + threadIdx.x;
    const float* base = p_w + (size_t)b * Cq * Cq + o;
    float s = 0.f;
    #pragma unroll 4
    for (int c = 0; c < Cq; ++c) {
        float v = base[(size_t)c * Cq];
        s = fmaf(v, v, s);
    }
    g_inv_pnorm[b * Cq + o] = 1.f / fmaxf(sqrtf(s), 1e-12f);
}

// Transpose p_w[b][c][o]*p_g[b][c] -> packed [b*1024+o rows][c cols] bf16 split
__global__ __launch_bounds__(256) void pw_prep_kernel(
    const float* __restrict__ p_w, const float* __restrict__ p_g) {
    int b = blockIdx.z;
    int c0 = blockIdx.x * 32;
    int o0 = blockIdx.y * 32;
    __shared__ float s[32][33];
    __shared__ float pgs[32];
    int tid = threadIdx.x;
    int x = tid & 31, y = tid >> 5;
    if (tid < 32) pgs[tid] = p_g[b * Cq + c0 + tid];
    const float* in = p_w + (size_t)b * Cq * Cq;
    #pragma unroll
    for (int yy = 0; yy < 4; ++yy) {
        int c = c0 + y * 4 + yy;
        s[y * 4 + yy][x] = in[(size_t)c * Cq + o0 + x];
    }
    __syncthreads();
    int q = c0 >> 5;
    int sseg = x >> 3;
    int ins = (x & 7) << 1;
    #pragma unroll
    for (int yy = 0; yy < 4; ++yy) {
        int o = o0 + y * 4 + yy;
        float w = s[x][y * 4 + yy] * pgs[x];
        __nv_bfloat16 h, l;
        bsplit(w, h, l);
        int m = (b << 3) | (o >> 7);
        size_t off = pk_off(m, q, o & 127, sseg, 32) + ins;
        *(__nv_bfloat16*)((char*)g_pwhi + off) = h;
        *(__nv_bfloat16*)((char*)g_pwlo + off) = l;
    }
}

// ===========================================================================
// Depthwise conv on [t][c] layout -> packed bf16 split
// ===========================================================================
__global__ __launch_bounds__(256) void conv_t_kernel(
    const float* __restrict__ d_w, const float* __restrict__ d_g,
    const float* __restrict__ d_b) {
    int b  = blockIdx.z;
    int t0 = blockIdx.y * 8;
    int ch = blockIdx.x * 512;
    __shared__ float s[16][512];
    const float* h = g_hT + (size_t)b * Tq * Cq;
    int tid = threadIdx.x;
    #pragma unroll
    for (int i = 0; i < 8; ++i) {
        int idx = tid + i * 256;
        int r  = idx >> 7;
        int cc = (idx & 127) * 4;
        int t = t0 - 4 + r;
        float4 v = (t >= 0 && t < Tq)
            ? *(const float4*)(h + (size_t)t * Cq + ch + cc)
            : make_float4(0.f, 0.f, 0.f, 0.f);
        *(float4*)&s[r][cc] = v;
    }
    __syncthreads();
    int cg = (tid & 127) * 4;
    int tsub = tid >> 7;
    int c = ch + cg;
    float w[Kq][4], bias[4];
    #pragma unroll
    for (int qd = 0; qd < 4; ++qd) {
        float g = d_g[b * Cq + c + qd];
        bias[qd] = d_b[b * Cq + c + qd];
        #pragma unroll
        for (int k = 0; k < Kq; ++k)
            w[k][qd] = d_w[((size_t)b * Cq + c + qd) * Kq + k] * g_inv_dnorm[b * Kq + k] * g;
    }
    int qc = c >> 5;
    int sc = (c >> 3) & 3;
    int ins = (c & 7) << 1;      // 0 or 8
    #pragma unroll
    for (int i = 0; i < 4; ++i) {
        int tl = tsub * 4 + i;
        int t = t0 + tl;
        float4 acc = make_float4(bias[0], bias[1], bias[2], bias[3]);
        #pragma unroll
        for (int k = 0; k < Kq; ++k) {
            float4 vv = *(float4*)&s[tl + k][cg];
            acc.x = fmaf(vv.x, w[k][0], acc.x);
            acc.y = fmaf(vv.y, w[k][1], acc.y);
            acc.z = fmaf(vv.z, w[k][2], acc.z);
            acc.w = fmaf(vv.w, w[k][3], acc.w);
        }
        __nv_bfloat16 h0, h1, h2, h3, l0, l1, l2, l3;
        bsplit(acc.x, h0, l0); bsplit(acc.y, h1, l1);
        bsplit(acc.z, h2, l2); bsplit(acc.w, h3, l3);
        int m = (b << 3) | (t >> 7);
        size_t off = pk_off(m, qc, t & 127, sc, 32) + ins;
        *(uint2*)((char*)g_convhi + off) = make_uint2(pkbf(h0,h1), pkbf(h2,h3));
        *(uint2*)((char*)g_convlo + off) = make_uint2(pkbf(l0,l1), pkbf(l2,l3));
    }
}

// ===========================================================================
// mma.sync bf16-split GEMM with cp.async.bulk chunk loads.
// CTA tile 128x128, K-chunk 32, 2 stages x 32KB, 2 CTAs/SM.
// Stage layout: [AH 8K][AL 8K][BH 8K][BL 8K]
// ===========================================================================
#define STAGE_B 32768
#define SMEM_ALLOC (1024 + 128 + 2 * STAGE_B)

__device__ __forceinline__ void issue_chunk(uint32_t st0, uint32_t mb0, uint32_t mb1,
    const char* Ah, const char* Al, const char* Bh, const char* Bl, int q) {
    uint32_t mb = (q & 1) ? mb1 : mb0;
    uint32_t dst = st0 + (uint32_t)(q & 1) * STAGE_B;
    size_t qo = (size_t)q << 13;
    mbar_expect(mb, 32768u);
    bulk_ld(dst,          Ah + qo, mb);
    bulk_ld(dst + 8192u,  Al + qo, mb);
    bulk_ld(dst + 16384u, Bh + qo, mb);
    bulk_ld(dst + 24576u, Bl + qo, mb);
}

template <int EPI>
__global__ __launch_bounds__(256, 2) void mma_gemm(
    const __nv_bfloat16* __restrict__ Ahi, const __nv_bfloat16* __restrict__ Alo,
    int a_mpb,
    const __nv_bfloat16* __restrict__ Bhi, const __nv_bfloat16* __restrict__ Blo,
    int b_mpb,
    int nchunks,
    const float* __restrict__ e0, const float* __restrict__ e1,
    float* __restrict__ out0) {
    extern __shared__ __align__(128) char dsm[];
    uint32_t raw = smem_to_u32(dsm);
    uint32_t hdr = (raw + 1023u) & ~1023u;
    uint32_t mb0 = hdr, mb1 = hdr + 8;
    uint32_t st0 = hdr + 128;
    int tid = threadIdx.x;
    int wid = tid >> 5, lane = tid & 31;
    int wm = wid >> 2, wn = wid & 3;          // warp grid 2(m) x 4(n)
    int b = blockIdx.z, m0 = blockIdx.y * 128, n0 = blockIdx.x * 128;

    const char* Abh = (const char*)Ahi + ((size_t)((b * a_mpb + blockIdx.y) * nchunks) << 13);
    const char* Abl = (const char*)Alo + ((size_t)((b * a_mpb + blockIdx.y) * nchunks) << 13);
    const char* Bbh = (const char*)Bhi + ((size_t)((b * b_mpb + blockIdx.x) * nchunks) << 13);
    const char* Bbl = (const char*)Blo + ((size_t)((b * b_mpb + blockIdx.x) * nchunks) << 13);

    if (tid == 0) { MBARRIER_INIT(mb0, 1); MBARRIER_INIT(mb1, 1); }
    __syncthreads();
    if (tid == 0) {
        issue_chunk(st0, mb0, mb1, Abh, Abl, Bbh, Bbl, 0);
        issue_chunk(st0, mb0, mb1, Abh, Abl, Bbh, Bbl, 1);
    }

    // ldmatrix tile-relative swizzled offsets.
    // A: aoff[i][ks] (X4 over 16 rows x 16k).
    // B: boff4[J][ks] (X4 over jj-pair {2J,2J+1}: 4 matrices = 2 n-tiles x 2 k-halves).
    uint32_t aoff[4][2], boff4[2][2];
    {
        int rla = lane & 15, sha = (lane >> 4) & 1;
        #pragma unroll
        for (int i = 0; i < 4; ++i) {
            int r = wm * 64 + i * 16 + rla;
            int p = r >> 1, x4 = (r & 1) << 2, mk = p & 7, rb = p << 7;
            aoff[i][0] = rb + (((x4 | sha) ^ mk) << 4);
            aoff[i][1] = rb + (((x4 | (2 + sha)) ^ mk) << 4);
        }
        int rlb = lane & 7;
        int shb = (lane >> 3) & 1;       // k half
        int jsel = (lane >> 4) & 1;      // which jj of the pair
        #pragma unroll
        for (int J = 0; J < 2; ++J) {
            int r = wn * 32 + (J * 2 + jsel) * 8 + rlb;
            int p = r >> 1, x4 = (r & 1) << 2, mk = p & 7, rb = p << 7;
            boff4[J][0] = rb + (((x4 | shb) ^ mk) << 4);
            boff4[J][1] = rb + (((x4 | (2 + shb)) ^ mk) << 4);
        }
    }

    float acc[4][4][4] = {};

    for (int q = 0; q < nchunks; ++q) {
        MBARRIER_WAIT_PARITY((q & 1) ? mb1 : mb0, (q >> 1) & 1);
        uint32_t st = st0 + (uint32_t)(q & 1) * STAGE_B;
        #pragma unroll
        for (int ks = 0; ks < 2; ++ks) {
            uint32_t ah[4][4], al[4][4], bh[4][2], bl[4][2];
            #pragma unroll
            for (int i = 0; i < 4; ++i) {
                LDSM_X4(ah[i], st + aoff[i][ks]);
                LDSM_X4(al[i], st + 8192u + aoff[i][ks]);
            }
            #pragma unroll
            for (int J = 0; J < 2; ++J) {
                LDSM_X4(&bh[J * 2][0], st + 16384u + boff4[J][ks]);
                LDSM_X4(&bl[J * 2][0], st + 24576u + boff4[J][ks]);
            }
            #pragma unroll
            for (int i = 0; i < 4; ++i)
                #pragma unroll
                for (int jj = 0; jj < 4; ++jj)
                    MMA_BF16(acc[i][jj], ah[i], bh[jj]);
            #pragma unroll
            for (int i = 0; i < 4; ++i)
                #pragma unroll
                for (int jj = 0; jj < 4; ++jj)
                    MMA_BF16(acc[i][jj], ah[i], bl[jj]);
            #pragma unroll
            for (int i = 0; i < 4; ++i)
                #pragma unroll
                for (int jj = 0; jj < 4; ++jj)
                    MMA_BF16(acc[i][jj], al[i], bh[jj]);
        }
        __syncthreads();   // all warps done reading buf(q&1) before its reuse
        if (q + 2 < nchunks && tid == 0)
            issue_chunk(st0, mb0, mb1, Abh, Abl, Bbh, Bbl, q + 2);
    }

    // Epilogue: frag (i,jj): c0 (r, col), c1 (r, col+1), c2 (r+8, col), c3 (r+8, col+1)
    int gid = lane >> 2, tig = lane & 3;
    #pragma unroll
    for (int i = 0; i < 4; ++i) {
        int r0 = m0 + wm * 64 + i * 16 + gid;
        #pragma unroll
        for (int jj = 0; jj < 4; ++jj) {
            int col = n0 + wn * 32 + jj * 8 + tig * 2;
            float v0 = acc[i][jj][0], v1 = acc[i][jj][1];
            float v2 = acc[i][jj][2], v3 = acc[i][jj][3];
            if (EPI == 1) {
                float b0 = e0[col], b1v = e0[col + 1];
                float* d0 = g_hT + ((size_t)b * Tq + r0) * Cq + col;
                float* d1 = g_hT + ((size_t)b * Tq + r0 + 8) * Cq + col;
                *(float2*)d0 = float2{mishf(v0 + b0), mishf(v1 + b1v)};
                *(float2*)d1 = float2{mishf(v2 + b0), mishf(v3 + b1v)};
            } else if (EPI == 2) {
                float s0 = g_inv_pnorm[b * Cq + col], s1 = g_inv_pnorm[b * Cq + col + 1];
                float p0 = e0[b * Cq + col], p1 = e0[b * Cq + col + 1];
                float u0 = mishf(fmaf(v0, s0, p0)), u1 = mishf(fmaf(v1, s1, p1));
                float u2 = mishf(fmaf(v2, s0, p0)), u3 = mishf(fmaf(v3, s1, p1));
                __nv_bfloat16 h0, h1, h2, h3, l0, l1, l2, l3;
                bsplit(u0, h0, l0); bsplit(u1, h1, l1);
                bsplit(u2, h2, l2); bsplit(u3, h3, l3);
                int m = (b << 3) | (r0 >> 7);
                int qp = col >> 5, sp = (col >> 3) & 3, ins = (col & 7) << 1;
                size_t oA = pk_off(m, qp, r0 & 127, sp, 32) + ins;
                size_t oB = pk_off(m, qp, (r0 + 8) & 127, sp, 32) + ins;
                *(uint32_t*)((char*)g_tmphi + oA) = pkbf(h0, h1);
                *(uint32_t*)((char*)g_tmphi + oB) = pkbf(h2, h3);
                *(uint32_t*)((char*)g_tmplo + oA) = pkbf(l0, l1);
                *(uint32_t*)((char*)g_tmplo + oB) = pkbf(l2, l3);
            } else {
                float b0 = e0[col], b1v = e0[col + 1];
                size_t o0i = ((size_t)b * Tq + r0) * Dq + col;
                size_t o1i = ((size_t)b * Tq + r0 + 8) * Dq + col;
                float2 x0 = *(const float2*)(e1 + o0i);
                float2 x1 = *(const float2*)(e1 + o1i);
                *(float2*)(out0 + o0i) = float2{v0 + b0 + x0.x, v1 + b1v + x0.y};
                *(float2*)(out0 + o1i) = float2{v2 + b0 + x1.x, v3 + b1v + x1.y};
            }
        }
    }
}

// ===========================================================================
extern "C" void kernel_launch(void* const* d_in, const int* in_sizes, int n_in,
                              void* d_out, int out_size) {
    const float* x   = (const float*)d_in[0];
    const float* d_w = (const float*)d_in[1];
    const float* d_g = (const float*)d_in[2];
    const float* d_b = (const float*)d_in[3];
    const float* p_w = (const float*)d_in[4];
    const float* p_g = (const float*)d_in[5];
    const float* p_b = (const float*)d_in[6];
    const float* w1  = (const float*)d_in[7];
    const float* b1  = (const float*)d_in[8];
    const float* w2  = (const float*)d_in[9];
    const float* b2  = (const float*)d_in[10];
    float* out = (float*)d_out;

    cudaFuncSetAttribute(mma_gemm<1>, cudaFuncAttributeMaxDynamicSharedMemorySize, SMEM_ALLOC);
    cudaFuncSetAttribute(mma_gemm<2>, cudaFuncAttributeMaxDynamicSharedMemorySize, SMEM_ALLOC);
    cudaFuncSetAttribute(mma_gemm<3>, cudaFuncAttributeMaxDynamicSharedMemorySize, SMEM_ALLOC);

    __nv_bfloat16 *xhi, *xlo, *w1hi, *w1lo, *w2hi, *w2lo;
    __nv_bfloat16 *convhi, *convlo, *pwhi, *pwlo, *tmphi, *tmplo;
    cudaGetSymbolAddress((void**)&xhi, g_xhi);
    cudaGetSymbolAddress((void**)&xlo, g_xlo);
    cudaGetSymbolAddress((void**)&w1hi, g_w1hi);
    cudaGetSymbolAddress((void**)&w1lo, g_w1lo);
    cudaGetSymbolAddress((void**)&w2hi, g_w2hi);
    cudaGetSymbolAddress((void**)&w2lo, g_w2lo);
    cudaGetSymbolAddress((void**)&convhi, g_convhi);
    cudaGetSymbolAddress((void**)&convlo, g_convlo);
    cudaGetSymbolAddress((void**)&pwhi, g_pwhi);
    cudaGetSymbolAddress((void**)&pwlo, g_pwlo);
    cudaGetSymbolAddress((void**)&tmphi, g_tmphi);
    cudaGetSymbolAddress((void**)&tmplo, g_tmplo);

    // Fork a side stream into the capture for independent prep work.
    cudaStream_t s2;
    cudaStreamCreateWithFlags(&s2, cudaStreamNonBlocking);
    cudaEvent_t eFork, eDn, eJoin;
    cudaEventCreateWithFlags(&eFork, cudaEventDisableTiming);
    cudaEventCreateWithFlags(&eDn,   cudaEventDisableTiming);
    cudaEventCreateWithFlags(&eJoin, cudaEventDisableTiming);

    cudaEventRecord(eFork, 0);
    cudaStreamWaitEvent(s2, eFork, 0);

    // Side stream: norms + p_w transpose + w2 split (independent of gemm1).
    dnorm_kernel<<<Bq * Kq, 256, 0, s2>>>(d_w);
    cudaEventRecord(eDn, s2);
    pnorm_kernel<<<dim3(Bq, Cq / 256), 256, 0, s2>>>(p_w);
    pw_prep_kernel<<<dim3(Cq / 32, Cq / 32, Bq), 256, 0, s2>>>(p_w, p_g);
    split_pack_kernel<<<(Dq * Cq / 8 + 255) / 256, 256, 0, s2>>>(w2, w2hi, w2lo, 7, 32, Dq * Cq / 8);
    cudaEventRecord(eJoin, s2);

    // Main stream: x/w1 splits -> GEMM1 -> conv -> GEMM2 -> GEMM3
    split_pack_kernel<<<(Bq * Tq * Dq / 8 + 255) / 256, 256>>>(x, xhi, xlo, 5, 8, Bq * Tq * Dq / 8);
    split_pack_kernel<<<(Cq * Dq / 8 + 255) / 256, 256>>>(w1, w1hi, w1lo, 5, 8, Cq * Dq / 8);

    // GEMM1: h = mish(x @ w1^T + b1)
    mma_gemm<1><<<dim3(Cq / 128, Tq / 128, Bq), 256, SMEM_ALLOC>>>(
        xhi, xlo, Tq / 128, w1hi, w1lo, 0, Dq / 32, b1, nullptr, nullptr);

    cudaStreamWaitEvent(0, eDn, 0);
    conv_t_kernel<<<dim3(Cq / 512, Tq / 8, Bq), 256>>>(d_w, d_g, d_b);

    cudaStreamWaitEvent(0, eJoin, 0);
    // GEMM2: tmp = mish(inv_pnorm*(conv @ pw^T) + p_b)
    mma_gemm<2><<<dim3(Cq / 128, Tq / 128, Bq), 256, SMEM_ALLOC>>>(
        convhi, convlo, Tq / 128, pwhi, pwlo, Cq / 128, Cq / 32, p_b, nullptr, nullptr);

    // GEMM3: out = tmp @ w2^T + b2 + x
    mma_gemm<3><<<dim3(Dq / 128, Tq / 128, Bq), 256, SMEM_ALLOC>>>(
        tmphi, tmplo, Tq / 128, w2hi, w2lo, 0, Cq / 32, b2, x, out);
}